// round 3
// baseline (speedup 1.0000x reference)
#include <cuda_runtime.h>
#include <math.h>
#include <stdint.h>

// ---------------- problem constants ----------------
#define Bb   2
#define Nn   2048
#define Dd   1024
#define Hh   16
#define DHh  64
#define Lv   3
#define BND  (Bb*Nn*Dd)          // 4,194,304 = 2^22 (exact power of two!)
#define HID_MAX 2816
#define NREDB 1024

// ---------------- scratch (device globals: the sanctioned no-alloc path) ----
__device__ float g_xn  [4096*1024];
__device__ float g_p1  [2048*1024];
__device__ float g_p2  [1024*1024];
__device__ float g_sc0 [4096*1024];
__device__ float g_sc1 [2048*1024];
__device__ float g_sc2 [1024*1024];
__device__ float g_q   [4096*1024];
__device__ float g_k   [4096*1024];
__device__ float g_v   [4096*1024];
__device__ float g_ao  [4096*1024];
__device__ float g_Z0  [4096*1024];
__device__ float g_Z1  [2048*1024];
__device__ float g_Z2  [1024*1024];
__device__ float g_x1  [4096*1024];
__device__ float g_gate[4096*HID_MAX];
__device__ float g_up  [4096*HID_MAX];
__device__ float  g_w  [4];      // nash weights, fp32 (bit-emulating XLA)
__device__ float  g_P  [8];      // [0..3]=sinkhorn(attn), [4..7]=sinkhorn(ffn)
__device__ double g_part[NREDB*3];

// correctly-rounded fp32 exp/log (via fp64; immune to -use_fast_math)
__device__ __forceinline__ float f32_exp(float x) { return (float)exp((double)x); }
__device__ __forceinline__ float f32_log(float x) { return (float)log((double)x); }

// emulate jax.nn.softmax on 3 fp32 values (x - max, exp, linear sum, divide)
__device__ __forceinline__ void softmax3_f32(float z0, float z1, float z2, float* w) {
    float m = fmaxf(z0, fmaxf(z1, z2));
    float e0 = f32_exp(z0 - m), e1 = f32_exp(z1 - m), e2 = f32_exp(z2 - m);
    float s = (e0 + e1) + e2;
    w[0] = e0 / s; w[1] = e1 / s; w[2] = e2 / s;
}

// ---------------- rmsnorm ----------------
__global__ void rmsnorm_k(const float* __restrict__ x, const float* __restrict__ w,
                          float* __restrict__ y) {
    int row = blockIdx.x;
    const float* xr = x + (size_t)row * Dd;
    float s = 0.f;
    for (int i = threadIdx.x; i < Dd; i += 256) { float v = xr[i]; s += v * v; }
    __shared__ float red[256];
    red[threadIdx.x] = s; __syncthreads();
    for (int o = 128; o > 0; o >>= 1) {
        if (threadIdx.x < o) red[threadIdx.x] += red[threadIdx.x + o];
        __syncthreads();
    }
    float r = rsqrtf(red[0] / (float)Dd + 1e-6f);
    float* yr = y + (size_t)row * Dd;
    for (int i = threadIdx.x; i < Dd; i += 256) yr[i] = xr[i] * w[i] * r;
}

// ---------------- avg-pool by 2 along seq (rows) ----------------
__global__ void pool_k(const float* __restrict__ in, float* __restrict__ out, int noutD) {
    int idx = blockIdx.x * 256 + threadIdx.x;
    if (idx >= noutD) return;
    int row = idx / Dd, d = idx % Dd;
    out[idx] = 0.5f * (in[(size_t)(2*row) * Dd + d] + in[(size_t)(2*row+1) * Dd + d]);
}

// ---------------- generic fp32 tiled GEMM: C[M,N] = A[M,K] @ B[K,N] --------
__global__ void sgemm_k(const float* __restrict__ A, const float* __restrict__ Bm,
                        float* __restrict__ C, int M, int N, int K) {
    __shared__ float As[16][68];   // [k][m], padded
    __shared__ float Bs[16][64];   // [k][n]
    int tid = threadIdx.x;
    int tx = tid & 15, ty = tid >> 4;
    int bm = blockIdx.y * 64, bn = blockIdx.x * 64;
    float acc[4][4] = {};
    for (int kb = 0; kb < K; kb += 16) {
        {
            int r0 = tid >> 4, c = tid & 15;
            #pragma unroll
            for (int i = 0; i < 4; i++) {
                int row = r0 + i * 16;
                int gr = bm + row, gc = kb + c;
                float val = (gr < M && gc < K) ? A[(size_t)gr * K + gc] : 0.f;
                As[c][row] = val;
            }
        }
        {
            int r0 = tid >> 6, c = tid & 63;
            #pragma unroll
            for (int i = 0; i < 4; i++) {
                int row = r0 + i * 4;
                int gr = kb + row, gc = bn + c;
                float val = (gr < K && gc < N) ? Bm[(size_t)gr * N + gc] : 0.f;
                Bs[row][c] = val;
            }
        }
        __syncthreads();
        #pragma unroll
        for (int kk = 0; kk < 16; kk++) {
            float4 a4 = *reinterpret_cast<const float4*>(&As[kk][ty * 4]);
            float4 b4 = *reinterpret_cast<const float4*>(&Bs[kk][tx * 4]);
            float a[4] = {a4.x, a4.y, a4.z, a4.w};
            float b[4] = {b4.x, b4.y, b4.z, b4.w};
            #pragma unroll
            for (int i = 0; i < 4; i++)
                #pragma unroll
                for (int j = 0; j < 4; j++) acc[i][j] += a[i] * b[j];
        }
        __syncthreads();
    }
    #pragma unroll
    for (int i = 0; i < 4; i++) {
        int gr = bm + ty * 4 + i;
        if (gr >= M) continue;
        #pragma unroll
        for (int j = 0; j < 4; j++) {
            int gc = bn + tx * 4 + j;
            if (gc < N) C[(size_t)gr * N + gc] = acc[i][j];
        }
    }
}

// ---------------- causal attention: one block per (qi, h, b) ----------------
__global__ void attn_k(const float* __restrict__ q, const float* __restrict__ k,
                       const float* __restrict__ v, float* __restrict__ o, int nl) {
    int qi = blockIdx.x, h = blockIdx.y, b = blockIdx.z;
    int t = threadIdx.x;                     // 128 threads
    __shared__ float qs[DHh];
    __shared__ float sc[2048];
    __shared__ float red[128];
    const size_t base = (size_t)b * nl * Dd + (size_t)h * DHh;
    if (t < DHh) qs[t] = q[base + (size_t)qi * Dd + t];
    __syncthreads();
    float lmax = -1e30f;
    for (int j = t; j <= qi; j += 128) {
        const float4* kr = reinterpret_cast<const float4*>(k + base + (size_t)j * Dd);
        float s = 0.f;
        #pragma unroll
        for (int dd = 0; dd < DHh / 4; dd++) {
            float4 kv = kr[dd];
            s += qs[dd*4+0]*kv.x + qs[dd*4+1]*kv.y + qs[dd*4+2]*kv.z + qs[dd*4+3]*kv.w;
        }
        s *= 0.125f;                         // 1/sqrt(64)
        sc[j] = s;
        lmax = fmaxf(lmax, s);
    }
    red[t] = lmax; __syncthreads();
    for (int o2 = 64; o2 > 0; o2 >>= 1) {
        if (t < o2) red[t] = fmaxf(red[t], red[t + o2]);
        __syncthreads();
    }
    float m = red[0]; __syncthreads();
    float lsum = 0.f;
    for (int j = t; j <= qi; j += 128) { float e = __expf(sc[j] - m); sc[j] = e; lsum += e; }
    red[t] = lsum; __syncthreads();
    for (int o2 = 64; o2 > 0; o2 >>= 1) {
        if (t < o2) red[t] += red[t + o2];
        __syncthreads();
    }
    float inv = 1.0f / red[0];
    __syncthreads();
    int d = t & 63, part = t >> 6;
    float acc = 0.f;
    for (int j = part; j <= qi; j += 2) acc += sc[j] * v[base + (size_t)j * Dd + d];
    red[t] = acc; __syncthreads();
    if (t < 64) o[base + (size_t)qi * Dd + d] = (red[t] + red[t + 64]) * inv;
}

// ---------------- small scalar kernels ----------------
__global__ void smalls_k(const float* aggl, const float* ml1, const float* ml2) {
    if (threadIdx.x || blockIdx.x) return;
    for (int s = 0; s < 2; s++) {
        const float* ml = s ? ml2 : ml1;
        float M0 = f32_exp(ml[0]), M1 = f32_exp(ml[1]), M2 = f32_exp(ml[2]), M3 = f32_exp(ml[3]);
        for (int it = 0; it < 10; it++) {
            float r0 = M0 + M1, r1 = M2 + M3;
            M0 /= r0; M1 /= r0; M2 /= r1; M3 /= r1;
            float c0 = M0 + M2, c1 = M1 + M3;
            M0 /= c0; M2 /= c0; M1 /= c1; M3 /= c1;
        }
        g_P[s*4+0] = M0; g_P[s*4+1] = M1; g_P[s*4+2] = M2; g_P[s*4+3] = M3;
    }
    // initial w = softmax(agg_logits), bit-emulated fp32 (zeros -> exactly fl(1/3))
    float w[3];
    softmax3_f32(aggl[0], aggl[1], aggl[2], w);
    g_w[0] = w[0]; g_w[1] = w[1]; g_w[2] = w[2];
}

// ---------------- nash: per-block partial MSE sums (fp64, deterministic) ----
// weights used for y_bar are double(w_fp32) so accumulation is accurate while
// matching the reference's fp32 w values
__global__ void nash_red_k() {
    double w0 = (double)g_w[0], w1 = (double)g_w[1], w2 = (double)g_w[2];
    double s0 = 0., s1 = 0., s2 = 0.;
    for (size_t idx = (size_t)blockIdx.x * 256 + threadIdx.x; idx < (size_t)BND;
         idx += (size_t)NREDB * 256) {
        size_t bn = idx / Dd; int d = (int)(idx % Dd);
        int b = (int)(bn / Nn), n = (int)(bn % Nn);
        double z0 = (double)g_Z0[idx];
        double z1 = (double)g_Z1[((size_t)b*(Nn/2) + (n>>1)) * Dd + d];
        double z2 = (double)g_Z2[((size_t)b*(Nn/4) + (n>>2)) * Dd + d];
        double yb = w0*z0 + w1*z1 + w2*z2;
        double d0 = z0-yb, d1 = z1-yb, d2 = z2-yb;
        s0 += d0*d0; s1 += d1*d1; s2 += d2*d2;
    }
    __shared__ double red[256];
    double sv[3] = {s0, s1, s2};
    for (int l = 0; l < 3; l++) {
        red[threadIdx.x] = sv[l]; __syncthreads();
        for (int o = 128; o > 0; o >>= 1) {
            if (threadIdx.x < o) red[threadIdx.x] += red[threadIdx.x + o];
            __syncthreads();
        }
        if (threadIdx.x == 0) g_part[blockIdx.x*3 + l] = red[0];
        __syncthreads();
    }
}

__global__ void nash_upd_k(const float* aggl) {
    if (threadIdx.x || blockIdx.x) return;
    double s0 = 0., s1 = 0., s2 = 0.;
    for (int i = 0; i < NREDB; i++) { s0 += g_part[i*3]; s1 += g_part[i*3+1]; s2 += g_part[i*3+2]; }
    // u = -mean(...); mean divides by 2^22 (exact). Cast to fp32 like XLA's fp32 u.
    float u0 = (float)(-(s0 * (1.0 / (double)BND)));
    float u1 = (float)(-(s1 * (1.0 / (double)BND)));
    float u2 = (float)(-(s2 * (1.0 / (double)BND)));
    // z = agg_logits + u (fp32 adds), then emulated fp32 softmax
    float w[3];
    softmax3_f32(aggl[0] + u0, aggl[1] + u1, aggl[2] + u2, w);
    g_w[0] = w[0]; g_w[1] = w[1]; g_w[2] = w[2];
}

// ---------------- residual mixes ----------------
__global__ void comb1_k(const float* __restrict__ x, float* __restrict__ x1) {
    size_t idx = (size_t)blockIdx.x * 256 + threadIdx.x;
    if (idx >= (size_t)BND) return;
    size_t bn = idx / Dd; int d = (int)(idx % Dd);
    int b = (int)(bn / Nn), n = (int)(bn % Nn);
    float ao = g_w[0]*g_Z0[idx]
             + g_w[1]*g_Z1[((size_t)b*(Nn/2) + (n>>1)) * Dd + d]
             + g_w[2]*g_Z2[((size_t)b*(Nn/4) + (n>>2)) * Dd + d];
    x1[idx] = g_P[0]*x[idx] + g_P[1]*ao;
}

__global__ void comb2_k(const float* __restrict__ x1, const float* __restrict__ ffn,
                        float* __restrict__ out) {
    size_t idx = (size_t)blockIdx.x * 256 + threadIdx.x;
    if (idx >= (size_t)BND) return;
    out[idx] = g_P[4]*x1[idx] + g_P[5]*ffn[idx];
}

__global__ void silu_mul_k(const float* __restrict__ g, const float* __restrict__ u,
                           float* __restrict__ h, long long n) {
    long long idx = (long long)blockIdx.x * 256 + threadIdx.x;
    if (idx >= n) return;
    float gv = g[idx];
    float sig = 1.0f / (1.0f + __expf(-gv));
    h[idx] = gv * sig * u[idx];
}

// ---------------- aux loss: bit-emulation of fp32 sum(w*log(w*3+1e-9)) ------
__global__ void aux_k(float* out) {
    if (threadIdx.x || blockIdx.x) return;
    float p[3];
    #pragma unroll
    for (int l = 0; l < 3; l++) {
        float w = g_w[l];
        float t = w * 3.0f;        // fp32 multiply (rounding matters!)
        t = t + 1e-9f;             // fp32 add
        float gl = f32_log(t);     // fp32 log
        p[l] = w * gl;             // fp32 multiply
    }
    out[BND] = (p[0] + p[1]) + p[2];   // fp32 linear sum
}

// ---------------- launcher ----------------
extern "C" void kernel_launch(void* const* d_in, const int* in_sizes, int n_in,
                              void* d_out, int out_size) {
    const float* x    = (const float*)d_in[0];
    const float* nw1  = (const float*)d_in[1];
    const float* nw2  = (const float*)d_in[2];
    const float* Wdec = (const float*)d_in[3];
    const float* Wq   = (const float*)d_in[4];
    const float* Wk   = (const float*)d_in[5];
    const float* Wv   = (const float*)d_in[6];
    const float* Wo   = (const float*)d_in[7];
    const float* aggl = (const float*)d_in[8];
    const float* wg   = (const float*)d_in[9];
    const float* wu   = (const float*)d_in[10];
    const float* wd   = (const float*)d_in[11];
    const float* ml1  = (const float*)d_in[12];
    const float* ml2  = (const float*)d_in[13];
    float* out = (float*)d_out;
    int HID = in_sizes[9] / Dd;          // 2734
    if (HID > HID_MAX) HID = HID_MAX;

    float *xn,*p1,*p2,*sc0,*sc1,*sc2,*q,*k,*v,*ao,*Z0,*Z1,*Z2,*x1,*gg,*gu;
    cudaGetSymbolAddress((void**)&xn,  g_xn);
    cudaGetSymbolAddress((void**)&p1,  g_p1);
    cudaGetSymbolAddress((void**)&p2,  g_p2);
    cudaGetSymbolAddress((void**)&sc0, g_sc0);
    cudaGetSymbolAddress((void**)&sc1, g_sc1);
    cudaGetSymbolAddress((void**)&sc2, g_sc2);
    cudaGetSymbolAddress((void**)&q,   g_q);
    cudaGetSymbolAddress((void**)&k,   g_k);
    cudaGetSymbolAddress((void**)&v,   g_v);
    cudaGetSymbolAddress((void**)&ao,  g_ao);
    cudaGetSymbolAddress((void**)&Z0,  g_Z0);
    cudaGetSymbolAddress((void**)&Z1,  g_Z1);
    cudaGetSymbolAddress((void**)&Z2,  g_Z2);
    cudaGetSymbolAddress((void**)&x1,  g_x1);
    cudaGetSymbolAddress((void**)&gg,  g_gate);
    cudaGetSymbolAddress((void**)&gu,  g_up);

    auto gemm = [&](const float* A, const float* Bm, float* C, int M, int N, int K) {
        dim3 g((N + 63) / 64, (M + 63) / 64);
        sgemm_k<<<g, 256>>>(A, Bm, C, M, N, K);
    };

    // sinkhorn P/P2 + nash w init (bit-emulated fp32)
    smalls_k<<<1, 32>>>(aggl, ml1, ml2);

    // rmsnorm + hierarchical decomposition
    rmsnorm_k<<<Bb*Nn, 256>>>(x, nw1, xn);
    gemm(xn, Wdec + 0*Dd*Dd, sc0, Bb*Nn,   Dd, Dd);
    pool_k<<<(Bb*(Nn/2)*Dd + 255)/256, 256>>>(xn, p1, Bb*(Nn/2)*Dd);
    gemm(p1, Wdec + 1*Dd*Dd, sc1, Bb*(Nn/2), Dd, Dd);
    pool_k<<<(Bb*(Nn/4)*Dd + 255)/256, 256>>>(p1, p2, Bb*(Nn/4)*Dd);
    gemm(p2, Wdec + 2*Dd*Dd, sc2, Bb*(Nn/4), Dd, Dd);

    // per-level attention; Wo applied at low resolution (commutes with repeat)
    const float* scs[3] = {sc0, sc1, sc2};
    float*       Zs[3]  = {Z0, Z1, Z2};
    int          nls[3] = {Nn, Nn/2, Nn/4};
    for (int l = 0; l < Lv; l++) {
        int nl = nls[l], M = Bb * nl;
        gemm(scs[l], Wq + (size_t)l*Dd*Dd, q, M, Dd, Dd);
        gemm(scs[l], Wk + (size_t)l*Dd*Dd, k, M, Dd, Dd);
        gemm(scs[l], Wv,                   v, M, Dd, Dd);
        attn_k<<<dim3(nl, Hh, Bb), 128>>>(q, k, v, ao, nl);
        gemm(ao, Wo, Zs[l], M, Dd, Dd);
    }

    // nash best-response iterations (fp64 reductions, fp32-emulated softmax)
    for (int it = 0; it < 3; it++) {
        nash_red_k<<<NREDB, 256>>>();
        nash_upd_k<<<1, 32>>>(aggl);
    }

    // mHC attention mix
    comb1_k<<<(BND + 255)/256, 256>>>(x, x1);

    // SwiGLU FFN
    rmsnorm_k<<<Bb*Nn, 256>>>(x1, nw2, xn);
    gemm(xn, wg, gg, Bb*Nn, HID, Dd);
    gemm(xn, wu, gu, Bb*Nn, HID, Dd);
    long long nh = (long long)Bb*Nn*HID;
    silu_mul_k<<<(unsigned)((nh + 255)/256), 256>>>(gg, gu, gg, nh);
    gemm(gg, wd, ao, Bb*Nn, Dd, HID);

    // mHC FFN mix -> d_out, then aux loss scalar
    comb2_k<<<(BND + 255)/256, 256>>>(x1, ao, out);
    if (out_size > BND) aux_k<<<1, 32>>>(out);
}

// round 4
// speedup vs baseline: 1.6034x; 1.6034x over previous
#include <cuda_runtime.h>
#include <math.h>
#include <stdint.h>

// ---------------- problem constants ----------------
#define Bb   2
#define Nn   2048
#define Dd   1024
#define Hh   16
#define DHh  64
#define Lv   3
#define BND  (Bb*Nn*Dd)          // 4,194,304 = 2^22
#define HID_MAX 2816
#define NREDB 1024

// ---------------- scratch ----------------
__device__ float g_xn  [4096*1024];
__device__ float g_p1  [2048*1024];
__device__ float g_p2  [1024*1024];
__device__ float g_sc0 [4096*1024];
__device__ float g_sc1 [2048*1024];
__device__ float g_sc2 [1024*1024];
__device__ float g_q   [4096*1024];
__device__ float g_k   [4096*1024];
__device__ float g_v   [4096*1024];
__device__ float g_ao  [4096*1024];
__device__ float g_Z0  [4096*1024];
__device__ float g_Z1  [2048*1024];
__device__ float g_Z2  [1024*1024];
__device__ float g_x1  [4096*1024];
__device__ float g_gate[4096*HID_MAX];
__device__ float g_up  [4096*HID_MAX];
__device__ float  g_w  [4];
__device__ float  g_P  [8];
__device__ double g_part[NREDB*3];

// correctly-rounded fp32 exp/log via fp64 (immune to fast-math)
__device__ __forceinline__ float f32_exp(float x) { return (float)exp((double)x); }
__device__ __forceinline__ float f32_log(float x) { return (float)log((double)x); }

__device__ __forceinline__ void softmax3_f32(float z0, float z1, float z2, float* w) {
    float m = fmaxf(z0, fmaxf(z1, z2));
    float e0 = f32_exp(z0 - m), e1 = f32_exp(z1 - m), e2 = f32_exp(z2 - m);
    float s = (e0 + e1) + e2;
    w[0] = e0 / s; w[1] = e1 / s; w[2] = e2 / s;
}

// ---------------- rmsnorm ----------------
__global__ void rmsnorm_k(const float* __restrict__ x, const float* __restrict__ w,
                          float* __restrict__ y) {
    int row = blockIdx.x;
    const float* xr = x + (size_t)row * Dd;
    float s = 0.f;
    for (int i = threadIdx.x; i < Dd; i += 256) { float v = xr[i]; s += v * v; }
    __shared__ float red[256];
    red[threadIdx.x] = s; __syncthreads();
    for (int o = 128; o > 0; o >>= 1) {
        if (threadIdx.x < o) red[threadIdx.x] += red[threadIdx.x + o];
        __syncthreads();
    }
    float r = rsqrtf(red[0] / (float)Dd + 1e-6f);
    float* yr = y + (size_t)row * Dd;
    for (int i = threadIdx.x; i < Dd; i += 256) yr[i] = xr[i] * w[i] * r;
}

// ---------------- avg-pool by 2 ----------------
__global__ void pool_k(const float* __restrict__ in, float* __restrict__ out, int noutD) {
    int idx = blockIdx.x * 256 + threadIdx.x;
    if (idx >= noutD) return;
    int row = idx / Dd, d = idx % Dd;
    out[idx] = 0.5f * (in[(size_t)(2*row) * Dd + d] + in[(size_t)(2*row+1) * Dd + d]);
}

// ---------------- fp32 GEMM: 128x128 tile, 8x8 micro, double-buffered ------
__global__ void __launch_bounds__(256, 2)
sgemm128_k(const float* __restrict__ A, const float* __restrict__ Bm,
           float* __restrict__ C, int M, int N, int K) {
    __shared__ float As[2][8][132];   // [buf][k][m]
    __shared__ float Bs[2][8][128];   // [buf][k][n]
    int tid = threadIdx.x;
    int bm = blockIdx.y * 128, bn = blockIdx.x * 128;
    int tx = tid & 15, ty = tid >> 4;
    int arow = tid >> 1, akq = (tid & 1) * 4;     // A: 128 rows x 8k
    int brow = tid >> 5, bcol = (tid & 31) * 4;   // B: 8 rows x 128n
    float acc[8][8] = {};
    int ntiles = (K + 7) / 8;
    float ra[4], rb[4];
    // preload tile 0
    {
        int gr = bm + arow;
        #pragma unroll
        for (int i = 0; i < 4; i++) {
            int gc = akq + i;
            As[0][akq + i][arow] = (gr < M && gc < K) ? A[(size_t)gr * K + gc] : 0.f;
        }
        int gcb = bn + bcol;
        float t[4];
        #pragma unroll
        for (int i = 0; i < 4; i++)
            t[i] = (brow < K && gcb + i < N) ? Bm[(size_t)brow * N + gcb + i] : 0.f;
        *(float4*)&Bs[0][brow][bcol] = make_float4(t[0], t[1], t[2], t[3]);
    }
    __syncthreads();
    for (int t = 0; t < ntiles; t++) {
        int cur = t & 1, nxt = cur ^ 1;
        if (t + 1 < ntiles) {
            int kb = (t + 1) * 8;
            int gr = bm + arow;
            #pragma unroll
            for (int i = 0; i < 4; i++) {
                int gc = kb + akq + i;
                ra[i] = (gr < M && gc < K) ? A[(size_t)gr * K + gc] : 0.f;
            }
            int grb = kb + brow, gcb = bn + bcol;
            #pragma unroll
            for (int i = 0; i < 4; i++)
                rb[i] = (grb < K && gcb + i < N) ? Bm[(size_t)grb * N + gcb + i] : 0.f;
        }
        #pragma unroll
        for (int kk = 0; kk < 8; kk++) {
            float4 a0 = *(const float4*)&As[cur][kk][ty * 8];
            float4 a1 = *(const float4*)&As[cur][kk][ty * 8 + 4];
            float4 b0 = *(const float4*)&Bs[cur][kk][tx * 8];
            float4 b1 = *(const float4*)&Bs[cur][kk][tx * 8 + 4];
            float a[8] = {a0.x, a0.y, a0.z, a0.w, a1.x, a1.y, a1.z, a1.w};
            float b[8] = {b0.x, b0.y, b0.z, b0.w, b1.x, b1.y, b1.z, b1.w};
            #pragma unroll
            for (int i = 0; i < 8; i++)
                #pragma unroll
                for (int j = 0; j < 8; j++) acc[i][j] += a[i] * b[j];
        }
        if (t + 1 < ntiles) {
            #pragma unroll
            for (int i = 0; i < 4; i++) As[nxt][akq + i][arow] = ra[i];
            *(float4*)&Bs[nxt][brow][bcol] = make_float4(rb[0], rb[1], rb[2], rb[3]);
        }
        __syncthreads();
    }
    #pragma unroll
    for (int i = 0; i < 8; i++) {
        int gr = bm + ty * 8 + i;
        if (gr >= M) continue;
        #pragma unroll
        for (int j = 0; j < 8; j++) {
            int gc = bn + tx * 8 + j;
            if (gc < N) C[(size_t)gr * N + gc] = acc[i][j];
        }
    }
}

// ---------------- flash attention: 64-query x 32-key tiles ------------------
// grid (nl/64, H, B), 256 threads. Q scaled on load. Online softmax.
__global__ void __launch_bounds__(256, 2)
fattn_k(const float* __restrict__ q, const float* __restrict__ k,
        const float* __restrict__ v, float* __restrict__ o, int nl) {
    __shared__ float Qs[64][68];      // [query][d]
    __shared__ float Kt[64][36];      // [d][key]   (transposed)
    __shared__ float Vs[32][68];      // [key][d]
    __shared__ float Ps[64][36];      // [query][key]
    int qt = blockIdx.x, h = blockIdx.y, b = blockIdx.z;
    int tid = threadIdx.x;
    int tx = tid & 15, ty = tid >> 4;
    const size_t base = (size_t)b * nl * Dd + (size_t)h * DHh;
    int q0 = qt * 64;
    // load Q tile (scaled by 1/sqrt(64))
    {
        int qr = tid >> 2, qc0 = (tid & 3) * 16;
        #pragma unroll
        for (int j = 0; j < 4; j++) {
            float4 t4 = *(const float4*)&q[base + (size_t)(q0 + qr) * Dd + qc0 + j * 4];
            t4.x *= 0.125f; t4.y *= 0.125f; t4.z *= 0.125f; t4.w *= 0.125f;
            *(float4*)&Qs[qr][qc0 + j * 4] = t4;
        }
    }
    float O[4][4] = {};
    float m[4], l[4];
    #pragma unroll
    for (int i = 0; i < 4; i++) { m[i] = -1e30f; l[i] = 0.f; }
    int nkt = 2 * qt + 2;
    for (int kt = 0; kt < nkt; kt++) {
        int k0 = kt * 32;
        // load K (transposed) + V tile
        {
            int kr = tid >> 3, dc0 = (tid & 7) * 8;
            #pragma unroll
            for (int jj = 0; jj < 8; jj++)
                Kt[dc0 + jj][kr] = k[base + (size_t)(k0 + kr) * Dd + dc0 + jj];
            if (kr < 32) {
                #pragma unroll
                for (int j = 0; j < 2; j++)
                    *(float4*)&Vs[kr][dc0 + j * 4] =
                        *(const float4*)&v[base + (size_t)(k0 + kr) * Dd + dc0 + j * 4];
            } else {
                int vr = kr - 32;
                #pragma unroll
                for (int j = 0; j < 2; j++)
                    *(float4*)&Vs[vr][dc0 + j * 4] =
                        *(const float4*)&v[base + (size_t)(k0 + vr) * Dd + dc0 + j * 4];
            }
        }
        __syncthreads();
        // S[4 rows][2 cols] = Q @ K^T
        float S[4][2] = {};
        #pragma unroll 4
        for (int d = 0; d < 64; d++) {
            float kv0 = Kt[d][tx * 2], kv1 = Kt[d][tx * 2 + 1];
            #pragma unroll
            for (int i = 0; i < 4; i++) {
                float qv = Qs[ty * 4 + i][d];
                S[i][0] += qv * kv0;
                S[i][1] += qv * kv1;
            }
        }
        // causal mask (only tiles straddling the diagonal)
        if (k0 + 31 > q0) {
            #pragma unroll
            for (int i = 0; i < 4; i++) {
                int qg = q0 + ty * 4 + i;
                #pragma unroll
                for (int j = 0; j < 2; j++)
                    if (k0 + tx * 2 + j > qg) S[i][j] = -1e30f;
            }
        }
        // online softmax update
        #pragma unroll
        for (int i = 0; i < 4; i++) {
            float rm = fmaxf(S[i][0], S[i][1]);
            #pragma unroll
            for (int off = 8; off > 0; off >>= 1)
                rm = fmaxf(rm, __shfl_xor_sync(0xffffffffu, rm, off));
            float mn = fmaxf(m[i], rm);
            float sc = __expf(m[i] - mn);
            float e0 = __expf(S[i][0] - mn);
            float e1 = __expf(S[i][1] - mn);
            S[i][0] = e0; S[i][1] = e1;
            float rs = e0 + e1;
            #pragma unroll
            for (int off = 8; off > 0; off >>= 1)
                rs += __shfl_xor_sync(0xffffffffu, rs, off);
            l[i] = l[i] * sc + rs;
            m[i] = mn;
            #pragma unroll
            for (int j = 0; j < 4; j++) O[i][j] *= sc;
        }
        // stage P
        #pragma unroll
        for (int i = 0; i < 4; i++) {
            Ps[ty * 4 + i][tx * 2]     = S[i][0];
            Ps[ty * 4 + i][tx * 2 + 1] = S[i][1];
        }
        __syncthreads();
        // O += P @ V
        #pragma unroll 4
        for (int c = 0; c < 32; c++) {
            float4 vv = *(const float4*)&Vs[c][tx * 4];
            #pragma unroll
            for (int i = 0; i < 4; i++) {
                float pv = Ps[ty * 4 + i][c];
                O[i][0] += pv * vv.x;
                O[i][1] += pv * vv.y;
                O[i][2] += pv * vv.z;
                O[i][3] += pv * vv.w;
            }
        }
        __syncthreads();
    }
    // write
    #pragma unroll
    for (int i = 0; i < 4; i++) {
        float inv = 1.0f / l[i];
        size_t orow = base + (size_t)(q0 + ty * 4 + i) * Dd + tx * 4;
        #pragma unroll
        for (int j = 0; j < 4; j++) o[orow + j] = O[i][j] * inv;
    }
}

// ---------------- small scalar kernels ----------------
__global__ void smalls_k(const float* aggl, const float* ml1, const float* ml2) {
    if (threadIdx.x || blockIdx.x) return;
    for (int s = 0; s < 2; s++) {
        const float* ml = s ? ml2 : ml1;
        float M0 = f32_exp(ml[0]), M1 = f32_exp(ml[1]), M2 = f32_exp(ml[2]), M3 = f32_exp(ml[3]);
        for (int it = 0; it < 10; it++) {
            float r0 = M0 + M1, r1 = M2 + M3;
            M0 /= r0; M1 /= r0; M2 /= r1; M3 /= r1;
            float c0 = M0 + M2, c1 = M1 + M3;
            M0 /= c0; M2 /= c0; M1 /= c1; M3 /= c1;
        }
        g_P[s*4+0] = M0; g_P[s*4+1] = M1; g_P[s*4+2] = M2; g_P[s*4+3] = M3;
    }
    float w[3];
    softmax3_f32(aggl[0], aggl[1], aggl[2], w);
    g_w[0] = w[0]; g_w[1] = w[1]; g_w[2] = w[2];
}

// ---------------- nash: fp64 deterministic reductions ----------------
__global__ void nash_red_k() {
    double w0 = (double)g_w[0], w1 = (double)g_w[1], w2 = (double)g_w[2];
    double s0 = 0., s1 = 0., s2 = 0.;
    for (size_t idx = (size_t)blockIdx.x * 256 + threadIdx.x; idx < (size_t)BND;
         idx += (size_t)NREDB * 256) {
        size_t bn = idx / Dd; int d = (int)(idx % Dd);
        int b = (int)(bn / Nn), n = (int)(bn % Nn);
        double z0 = (double)g_Z0[idx];
        double z1 = (double)g_Z1[((size_t)b*(Nn/2) + (n>>1)) * Dd + d];
        double z2 = (double)g_Z2[((size_t)b*(Nn/4) + (n>>2)) * Dd + d];
        double yb = w0*z0 + w1*z1 + w2*z2;
        double d0 = z0-yb, d1 = z1-yb, d2 = z2-yb;
        s0 += d0*d0; s1 += d1*d1; s2 += d2*d2;
    }
    __shared__ double red[256];
    double sv[3] = {s0, s1, s2};
    for (int lvl = 0; lvl < 3; lvl++) {
        red[threadIdx.x] = sv[lvl]; __syncthreads();
        for (int o = 128; o > 0; o >>= 1) {
            if (threadIdx.x < o) red[threadIdx.x] += red[threadIdx.x + o];
            __syncthreads();
        }
        if (threadIdx.x == 0) g_part[blockIdx.x*3 + lvl] = red[0];
        __syncthreads();
    }
}

__global__ void nash_upd_k(const float* aggl) {
    if (threadIdx.x || blockIdx.x) return;
    double s0 = 0., s1 = 0., s2 = 0.;
    for (int i = 0; i < NREDB; i++) { s0 += g_part[i*3]; s1 += g_part[i*3+1]; s2 += g_part[i*3+2]; }
    float u0 = (float)(-(s0 * (1.0 / (double)BND)));
    float u1 = (float)(-(s1 * (1.0 / (double)BND)));
    float u2 = (float)(-(s2 * (1.0 / (double)BND)));
    float w[3];
    softmax3_f32(aggl[0] + u0, aggl[1] + u1, aggl[2] + u2, w);
    g_w[0] = w[0]; g_w[1] = w[1]; g_w[2] = w[2];
}

// ---------------- residual mixes ----------------
__global__ void comb1_k(const float* __restrict__ x, float* __restrict__ x1) {
    size_t idx = (size_t)blockIdx.x * 256 + threadIdx.x;
    if (idx >= (size_t)BND) return;
    size_t bn = idx / Dd; int d = (int)(idx % Dd);
    int b = (int)(bn / Nn), n = (int)(bn % Nn);
    float ao = g_w[0]*g_Z0[idx]
             + g_w[1]*g_Z1[((size_t)b*(Nn/2) + (n>>1)) * Dd + d]
             + g_w[2]*g_Z2[((size_t)b*(Nn/4) + (n>>2)) * Dd + d];
    x1[idx] = g_P[0]*x[idx] + g_P[1]*ao;
}

__global__ void comb2_k(const float* __restrict__ x1, const float* __restrict__ ffn,
                        float* __restrict__ out) {
    size_t idx = (size_t)blockIdx.x * 256 + threadIdx.x;
    if (idx >= (size_t)BND) return;
    out[idx] = g_P[4]*x1[idx] + g_P[5]*ffn[idx];
}

__global__ void silu_mul_k(const float* __restrict__ g, const float* __restrict__ u,
                           float* __restrict__ h, long long n) {
    long long idx = (long long)blockIdx.x * 256 + threadIdx.x;
    if (idx >= n) return;
    float gv = g[idx];
    float sig = 1.0f / (1.0f + __expf(-gv));
    h[idx] = gv * sig * u[idx];
}

// ---------------- aux loss: fp32 bit-emulation ----------------
__global__ void aux_k(float* out) {
    if (threadIdx.x || blockIdx.x) return;
    float p[3];
    #pragma unroll
    for (int l = 0; l < 3; l++) {
        float w = g_w[l];
        float t = w * 3.0f;
        t = t + 1e-9f;
        float gl = f32_log(t);
        p[l] = w * gl;
    }
    out[BND] = (p[0] + p[1]) + p[2];
}

// ---------------- launcher ----------------
extern "C" void kernel_launch(void* const* d_in, const int* in_sizes, int n_in,
                              void* d_out, int out_size) {
    const float* x    = (const float*)d_in[0];
    const float* nw1  = (const float*)d_in[1];
    const float* nw2  = (const float*)d_in[2];
    const float* Wdec = (const float*)d_in[3];
    const float* Wq   = (const float*)d_in[4];
    const float* Wk   = (const float*)d_in[5];
    const float* Wv   = (const float*)d_in[6];
    const float* Wo   = (const float*)d_in[7];
    const float* aggl = (const float*)d_in[8];
    const float* wg   = (const float*)d_in[9];
    const float* wu   = (const float*)d_in[10];
    const float* wd   = (const float*)d_in[11];
    const float* ml1  = (const float*)d_in[12];
    const float* ml2  = (const float*)d_in[13];
    float* out = (float*)d_out;
    int HID = in_sizes[9] / Dd;
    if (HID > HID_MAX) HID = HID_MAX;

    float *xn,*p1,*p2,*sc0,*sc1,*sc2,*q,*k,*v,*ao,*Z0,*Z1,*Z2,*x1,*gg,*gu;
    cudaGetSymbolAddress((void**)&xn,  g_xn);
    cudaGetSymbolAddress((void**)&p1,  g_p1);
    cudaGetSymbolAddress((void**)&p2,  g_p2);
    cudaGetSymbolAddress((void**)&sc0, g_sc0);
    cudaGetSymbolAddress((void**)&sc1, g_sc1);
    cudaGetSymbolAddress((void**)&sc2, g_sc2);
    cudaGetSymbolAddress((void**)&q,   g_q);
    cudaGetSymbolAddress((void**)&k,   g_k);
    cudaGetSymbolAddress((void**)&v,   g_v);
    cudaGetSymbolAddress((void**)&ao,  g_ao);
    cudaGetSymbolAddress((void**)&Z0,  g_Z0);
    cudaGetSymbolAddress((void**)&Z1,  g_Z1);
    cudaGetSymbolAddress((void**)&Z2,  g_Z2);
    cudaGetSymbolAddress((void**)&x1,  g_x1);
    cudaGetSymbolAddress((void**)&gg,  g_gate);
    cudaGetSymbolAddress((void**)&gu,  g_up);

    auto gemm = [&](const float* A, const float* Bm, float* C, int M, int N, int K) {
        dim3 g((N + 127) / 128, (M + 127) / 128);
        sgemm128_k<<<g, 256>>>(A, Bm, C, M, N, K);
    };

    smalls_k<<<1, 32>>>(aggl, ml1, ml2);

    rmsnorm_k<<<Bb*Nn, 256>>>(x, nw1, xn);
    gemm(xn, Wdec + 0*Dd*Dd, sc0, Bb*Nn,   Dd, Dd);
    pool_k<<<(Bb*(Nn/2)*Dd + 255)/256, 256>>>(xn, p1, Bb*(Nn/2)*Dd);
    gemm(p1, Wdec + 1*Dd*Dd, sc1, Bb*(Nn/2), Dd, Dd);
    pool_k<<<(Bb*(Nn/4)*Dd + 255)/256, 256>>>(p1, p2, Bb*(Nn/4)*Dd);
    gemm(p2, Wdec + 2*Dd*Dd, sc2, Bb*(Nn/4), Dd, Dd);

    const float* scs[3] = {sc0, sc1, sc2};
    float*       Zs[3]  = {Z0, Z1, Z2};
    int          nls[3] = {Nn, Nn/2, Nn/4};
    for (int l = 0; l < Lv; l++) {
        int nl = nls[l], M = Bb * nl;
        gemm(scs[l], Wq + (size_t)l*Dd*Dd, q, M, Dd, Dd);
        gemm(scs[l], Wk + (size_t)l*Dd*Dd, k, M, Dd, Dd);
        gemm(scs[l], Wv,                   v, M, Dd, Dd);
        fattn_k<<<dim3(nl/64, Hh, Bb), 256>>>(q, k, v, ao, nl);
        gemm(ao, Wo, Zs[l], M, Dd, Dd);
    }

    for (int it = 0; it < 3; it++) {
        nash_red_k<<<NREDB, 256>>>();
        nash_upd_k<<<1, 32>>>(aggl);
    }

    comb1_k<<<(BND + 255)/256, 256>>>(x, x1);

    rmsnorm_k<<<Bb*Nn, 256>>>(x1, nw2, xn);
    gemm(xn, wg, gg, Bb*Nn, HID, Dd);
    gemm(xn, wu, gu, Bb*Nn, HID, Dd);
    long long nh = (long long)Bb*Nn*HID;
    silu_mul_k<<<(unsigned)((nh + 255)/256), 256>>>(gg, gu, gg, nh);
    gemm(gg, wd, ao, Bb*Nn, Dd, HID);

    comb2_k<<<(BND + 255)/256, 256>>>(x1, ao, out);
    if (out_size > BND) aux_k<<<1, 32>>>(out);
}

// round 6
// speedup vs baseline: 1.6791x; 1.0472x over previous
#include <cuda_runtime.h>
#include <cuda_bf16.h>
#include <mma.h>
#include <math.h>
#include <stdint.h>

// ---------------- problem constants ----------------
#define Bb   2
#define Nn   2048
#define Dd   1024
#define Hh   16
#define DHh  64
#define Lv   3
#define BND  (Bb*Nn*Dd)          // 4,194,304 = 2^22
#define HID_MAX 2816
#define HIDP 2816
#define NREDB 1024
#define APLANE (4096*2752)
#define BPLANE (2816*2752)

// ---------------- scratch ----------------
__device__ float g_xn  [4096*1024];
__device__ float g_p1  [2048*1024];
__device__ float g_p2  [1024*1024];
__device__ float g_sc0 [4096*1024];
__device__ float g_sc1 [2048*1024];
__device__ float g_sc2 [1024*1024];
__device__ float g_q   [4096*1024];
__device__ float g_k   [4096*1024];
__device__ float g_v   [4096*1024];
__device__ float g_ao  [4096*1024];
__device__ float g_Z0  [4096*1024];
__device__ float g_Z1  [2048*1024];
__device__ float g_Z2  [1024*1024];
__device__ float g_x1  [4096*1024];
__device__ float g_gate[4096*HID_MAX];
__device__ float g_up  [4096*HID_MAX];
__device__ float  g_w  [4];
__device__ float  g_P  [8];
__device__ double g_part[NREDB*3];
// bf16 split planes (16B-aligned for uint4 access)
__device__ __align__(128) __nv_bfloat16 g_Ah[APLANE];
__device__ __align__(128) __nv_bfloat16 g_Am[APLANE];
__device__ __align__(128) __nv_bfloat16 g_Al[APLANE];
__device__ __align__(128) __nv_bfloat16 g_Bh[BPLANE];
__device__ __align__(128) __nv_bfloat16 g_Bm[BPLANE];
__device__ __align__(128) __nv_bfloat16 g_Bl[BPLANE];

// plane-pair schedule: [sel][pair] (sel 0: 2-split, 3 pairs; sel 1: 3-split, 6 pairs)
__device__ const signed char c_PA[2][6] = {{0,1,0,0,0,0},{0,1,0,2,1,0}};
__device__ const signed char c_PB[2][6] = {{0,0,1,0,0,0},{0,0,1,0,1,2}};

// correctly-rounded fp32 exp/log via fp64 (immune to fast-math)
__device__ __forceinline__ float f32_exp(float x) { return (float)exp((double)x); }
__device__ __forceinline__ float f32_log(float x) { return (float)log((double)x); }

__device__ __forceinline__ void softmax3_f32(float z0, float z1, float z2, float* w) {
    float m = fmaxf(z0, fmaxf(z1, z2));
    float e0 = f32_exp(z0 - m), e1 = f32_exp(z1 - m), e2 = f32_exp(z2 - m);
    float s = (e0 + e1) + e2;
    w[0] = e0 / s; w[1] = e1 / s; w[2] = e2 / s;
}

// ---------------- split conversion kernels ----------------
__global__ void convA_k(const float* __restrict__ src, int M, int K, int Kp,
                        int stride, int three) {
    int idx = blockIdx.x * 256 + threadIdx.x;
    if (idx >= M * Kp) return;
    int r = idx / Kp, c = idx % Kp;
    float x = (c < K) ? src[(size_t)r * stride + c] : 0.f;
    __nv_bfloat16 hh = __float2bfloat16(x);
    float r1 = x - __bfloat162float(hh);
    g_Ah[idx] = hh;
    if (three) {
        __nv_bfloat16 mm = __float2bfloat16(r1);
        g_Am[idx] = mm;
        g_Al[idx] = __float2bfloat16(r1 - __bfloat162float(mm));
    } else {
        g_Am[idx] = __float2bfloat16(r1);
    }
}

// weights: [K,N] fp32 -> transposed [Np,Kp] bf16 planes (zero padded)
__global__ void convB_k(const float* __restrict__ src, int K, int N, int Kp, int Np, int three) {
    __shared__ float t[32][33];
    int kt = blockIdx.y * 32, nt = blockIdx.x * 32;
    int tx = threadIdx.x, ty = threadIdx.y;   // 32 x 8
    for (int i = ty; i < 32; i += 8) {
        int kk = kt + i, nn = nt + tx;
        t[i][tx] = (kk < K && nn < N) ? src[(size_t)kk * N + nn] : 0.f;
    }
    __syncthreads();
    for (int i = ty; i < 32; i += 8) {
        int nn = nt + i, kk = kt + tx;
        if (nn < Np && kk < Kp) {
            float x = t[tx][i];
            size_t o = (size_t)nn * Kp + kk;
            __nv_bfloat16 hh = __float2bfloat16(x);
            float r1 = x - __bfloat162float(hh);
            g_Bh[o] = hh;
            if (three) {
                __nv_bfloat16 mm = __float2bfloat16(r1);
                g_Bm[o] = mm;
                g_Bl[o] = __float2bfloat16(r1 - __bfloat162float(mm));
            } else {
                g_Bm[o] = __float2bfloat16(r1);
            }
        }
    }
}

// ---------------- wmma bf16 split GEMM: C[M,*] = A @ B^T(planes) ------------
// grid (Npad/128, M/128), 256 threads. Kp mult of 32. ldc = C row stride.
__global__ void __launch_bounds__(256)
wgemm_k(float* __restrict__ C, int M, int ldc, int Kp, int npairs) {
    using namespace nvcuda;
    __shared__ __nv_bfloat16 As[2][128][40];
    __shared__ __nv_bfloat16 Bs[2][128][40];
    int tid = threadIdx.x, wid = tid >> 5;
    int bm = blockIdx.y * 128, bn = blockIdx.x * 128;
    int wm = wid & 3, wn = wid >> 2;          // warp tile 32(m) x 64(n)
    int row = tid >> 1, cq = (tid & 1) * 16;  // loader mapping
    const __nv_bfloat16* Ap[3] = { g_Ah, g_Am, g_Al };
    const __nv_bfloat16* Bp[3] = { g_Bh, g_Bm, g_Bl };
    int sel = (npairs == 6) ? 1 : 0;
    int kchunks = Kp >> 5;
    int total = npairs * kchunks;

    wmma::fragment<wmma::accumulator, 16, 16, 16, float> acc[2][4];
    #pragma unroll
    for (int i = 0; i < 2; i++)
        #pragma unroll
        for (int j = 0; j < 4; j++) wmma::fill_fragment(acc[i][j], 0.f);

    // preload chunk 0
    {
        const __nv_bfloat16* Ag = Ap[c_PA[sel][0]];
        const __nv_bfloat16* Bg = Bp[c_PB[sel][0]];
        const __nv_bfloat16* ar = Ag + (size_t)(bm + row) * Kp + cq;
        const __nv_bfloat16* br = Bg + (size_t)(bn + row) * Kp + cq;
        *(uint4*)&As[0][row][cq]     = *(const uint4*)ar;
        *(uint4*)&As[0][row][cq + 8] = *(const uint4*)(ar + 8);
        *(uint4*)&Bs[0][row][cq]     = *(const uint4*)br;
        *(uint4*)&Bs[0][row][cq + 8] = *(const uint4*)(br + 8);
    }
    __syncthreads();

    for (int c = 0; c < total; c++) {
        int cur = c & 1;
        uint4 ra0, ra1, rb0, rb1;
        bool more = (c + 1 < total);
        if (more) {
            int pr = (c + 1) / kchunks, kc = ((c + 1) % kchunks) * 32;
            const __nv_bfloat16* Ag = Ap[c_PA[sel][pr]];
            const __nv_bfloat16* Bg = Bp[c_PB[sel][pr]];
            const __nv_bfloat16* ar = Ag + (size_t)(bm + row) * Kp + kc + cq;
            const __nv_bfloat16* br = Bg + (size_t)(bn + row) * Kp + kc + cq;
            ra0 = *(const uint4*)ar; ra1 = *(const uint4*)(ar + 8);
            rb0 = *(const uint4*)br; rb1 = *(const uint4*)(br + 8);
        }
        #pragma unroll
        for (int ks = 0; ks < 2; ks++) {
            wmma::fragment<wmma::matrix_a, 16, 16, 16, __nv_bfloat16, wmma::row_major> af[2];
            wmma::fragment<wmma::matrix_b, 16, 16, 16, __nv_bfloat16, wmma::col_major> bf[4];
            wmma::load_matrix_sync(af[0], &As[cur][wm * 32][ks * 16], 40);
            wmma::load_matrix_sync(af[1], &As[cur][wm * 32 + 16][ks * 16], 40);
            #pragma unroll
            for (int j = 0; j < 4; j++)
                wmma::load_matrix_sync(bf[j], &Bs[cur][wn * 64 + j * 16][ks * 16], 40);
            #pragma unroll
            for (int i = 0; i < 2; i++)
                #pragma unroll
                for (int j = 0; j < 4; j++)
                    wmma::mma_sync(acc[i][j], af[i], bf[j], acc[i][j]);
        }
        if (more) {
            int nxt = cur ^ 1;
            *(uint4*)&As[nxt][row][cq]     = ra0;
            *(uint4*)&As[nxt][row][cq + 8] = ra1;
            *(uint4*)&Bs[nxt][row][cq]     = rb0;
            *(uint4*)&Bs[nxt][row][cq + 8] = rb1;
        }
        __syncthreads();
    }
    #pragma unroll
    for (int i = 0; i < 2; i++)
        #pragma unroll
        for (int j = 0; j < 4; j++) {
            int r = bm + wm * 32 + i * 16, cc = bn + wn * 64 + j * 16;
            wmma::store_matrix_sync(&C[(size_t)r * ldc + cc], acc[i][j], ldc,
                                    wmma::mem_row_major);
        }
}

// ---------------- rmsnorm ----------------
__global__ void rmsnorm_k(const float* __restrict__ x, const float* __restrict__ w,
                          float* __restrict__ y) {
    int row = blockIdx.x;
    const float* xr = x + (size_t)row * Dd;
    float s = 0.f;
    for (int i = threadIdx.x; i < Dd; i += 256) { float v = xr[i]; s += v * v; }
    __shared__ float red[256];
    red[threadIdx.x] = s; __syncthreads();
    for (int o = 128; o > 0; o >>= 1) {
        if (threadIdx.x < o) red[threadIdx.x] += red[threadIdx.x + o];
        __syncthreads();
    }
    float r = rsqrtf(red[0] / (float)Dd + 1e-6f);
    float* yr = y + (size_t)row * Dd;
    for (int i = threadIdx.x; i < Dd; i += 256) yr[i] = xr[i] * w[i] * r;
}

// ---------------- avg-pool by 2 ----------------
__global__ void pool_k(const float* __restrict__ in, float* __restrict__ out, int noutD) {
    int idx = blockIdx.x * 256 + threadIdx.x;
    if (idx >= noutD) return;
    int row = idx / Dd, d = idx % Dd;
    out[idx] = 0.5f * (in[(size_t)(2*row) * Dd + d] + in[(size_t)(2*row+1) * Dd + d]);
}

// ---------------- flash attention (fp32) -----------------
__global__ void __launch_bounds__(256, 2)
fattn_k(const float* __restrict__ q, const float* __restrict__ k,
        const float* __restrict__ v, float* __restrict__ o, int nl) {
    __shared__ float Qs[64][68];
    __shared__ float Kt[64][36];
    __shared__ float Vs[32][68];
    __shared__ float Ps[64][36];
    int qt = blockIdx.x, h = blockIdx.y, b = blockIdx.z;
    int tid = threadIdx.x;
    int tx = tid & 15, ty = tid >> 4;
    const size_t base = (size_t)b * nl * Dd + (size_t)h * DHh;
    int q0 = qt * 64;
    {
        int qr = tid >> 2, qc0 = (tid & 3) * 16;
        #pragma unroll
        for (int j = 0; j < 4; j++) {
            float4 t4 = *(const float4*)&q[base + (size_t)(q0 + qr) * Dd + qc0 + j * 4];
            t4.x *= 0.125f; t4.y *= 0.125f; t4.z *= 0.125f; t4.w *= 0.125f;
            *(float4*)&Qs[qr][qc0 + j * 4] = t4;
        }
    }
    float O[4][4] = {};
    float m[4], l[4];
    #pragma unroll
    for (int i = 0; i < 4; i++) { m[i] = -1e30f; l[i] = 0.f; }
    int nkt = 2 * qt + 2;
    for (int kt = 0; kt < nkt; kt++) {
        int k0 = kt * 32;
        {
            int kr = tid >> 3, dc0 = (tid & 7) * 8;
            #pragma unroll
            for (int jj = 0; jj < 8; jj++)
                Kt[dc0 + jj][kr] = k[base + (size_t)(k0 + kr) * Dd + dc0 + jj];
            int vr = (kr < 32) ? kr : kr - 32;
            #pragma unroll
            for (int j = 0; j < 2; j++)
                *(float4*)&Vs[vr][dc0 + j * 4] =
                    *(const float4*)&v[base + (size_t)(k0 + vr) * Dd + dc0 + j * 4];
        }
        __syncthreads();
        float S[4][2] = {};
        #pragma unroll 4
        for (int d = 0; d < 64; d++) {
            float kv0 = Kt[d][tx * 2], kv1 = Kt[d][tx * 2 + 1];
            #pragma unroll
            for (int i = 0; i < 4; i++) {
                float qv = Qs[ty * 4 + i][d];
                S[i][0] += qv * kv0;
                S[i][1] += qv * kv1;
            }
        }
        if (k0 + 31 > q0) {
            #pragma unroll
            for (int i = 0; i < 4; i++) {
                int qg = q0 + ty * 4 + i;
                #pragma unroll
                for (int j = 0; j < 2; j++)
                    if (k0 + tx * 2 + j > qg) S[i][j] = -1e30f;
            }
        }
        #pragma unroll
        for (int i = 0; i < 4; i++) {
            float rm = fmaxf(S[i][0], S[i][1]);
            #pragma unroll
            for (int off = 8; off > 0; off >>= 1)
                rm = fmaxf(rm, __shfl_xor_sync(0xffffffffu, rm, off));
            float mn = fmaxf(m[i], rm);
            float sc = __expf(m[i] - mn);
            float e0 = __expf(S[i][0] - mn);
            float e1 = __expf(S[i][1] - mn);
            S[i][0] = e0; S[i][1] = e1;
            float rs = e0 + e1;
            #pragma unroll
            for (int off = 8; off > 0; off >>= 1)
                rs += __shfl_xor_sync(0xffffffffu, rs, off);
            l[i] = l[i] * sc + rs;
            m[i] = mn;
            #pragma unroll
            for (int j = 0; j < 4; j++) O[i][j] *= sc;
        }
        #pragma unroll
        for (int i = 0; i < 4; i++) {
            Ps[ty * 4 + i][tx * 2]     = S[i][0];
            Ps[ty * 4 + i][tx * 2 + 1] = S[i][1];
        }
        __syncthreads();
        #pragma unroll 4
        for (int c = 0; c < 32; c++) {
            float4 vv = *(const float4*)&Vs[c][tx * 4];
            #pragma unroll
            for (int i = 0; i < 4; i++) {
                float pv = Ps[ty * 4 + i][c];
                O[i][0] += pv * vv.x;
                O[i][1] += pv * vv.y;
                O[i][2] += pv * vv.z;
                O[i][3] += pv * vv.w;
            }
        }
        __syncthreads();
    }
    #pragma unroll
    for (int i = 0; i < 4; i++) {
        float inv = 1.0f / l[i];
        size_t orow = base + (size_t)(q0 + ty * 4 + i) * Dd + tx * 4;
        #pragma unroll
        for (int j = 0; j < 4; j++) o[orow + j] = O[i][j] * inv;
    }
}

// ---------------- small scalar kernels ----------------
__global__ void smalls_k(const float* aggl, const float* ml1, const float* ml2) {
    if (threadIdx.x || blockIdx.x) return;
    for (int s = 0; s < 2; s++) {
        const float* ml = s ? ml2 : ml1;
        float M0 = f32_exp(ml[0]), M1 = f32_exp(ml[1]), M2 = f32_exp(ml[2]), M3 = f32_exp(ml[3]);
        for (int it = 0; it < 10; it++) {
            float r0 = M0 + M1, r1 = M2 + M3;
            M0 /= r0; M1 /= r0; M2 /= r1; M3 /= r1;
            float c0 = M0 + M2, c1 = M1 + M3;
            M0 /= c0; M2 /= c0; M1 /= c1; M3 /= c1;
        }
        g_P[s*4+0] = M0; g_P[s*4+1] = M1; g_P[s*4+2] = M2; g_P[s*4+3] = M3;
    }
    float w[3];
    softmax3_f32(aggl[0], aggl[1], aggl[2], w);
    g_w[0] = w[0]; g_w[1] = w[1]; g_w[2] = w[2];
}

// ---------------- nash: fp64 deterministic reductions ----------------
__global__ void nash_red_k() {
    double w0 = (double)g_w[0], w1 = (double)g_w[1], w2 = (double)g_w[2];
    double s0 = 0., s1 = 0., s2 = 0.;
    for (size_t idx = (size_t)blockIdx.x * 256 + threadIdx.x; idx < (size_t)BND;
         idx += (size_t)NREDB * 256) {
        size_t bn = idx / Dd; int d = (int)(idx % Dd);
        int b = (int)(bn / Nn), n = (int)(bn % Nn);
        double z0 = (double)g_Z0[idx];
        double z1 = (double)g_Z1[((size_t)b*(Nn/2) + (n>>1)) * Dd + d];
        double z2 = (double)g_Z2[((size_t)b*(Nn/4) + (n>>2)) * Dd + d];
        double yb = w0*z0 + w1*z1 + w2*z2;
        double d0 = z0-yb, d1 = z1-yb, d2 = z2-yb;
        s0 += d0*d0; s1 += d1*d1; s2 += d2*d2;
    }
    __shared__ double red[256];
    double sv[3] = {s0, s1, s2};
    for (int lvl = 0; lvl < 3; lvl++) {
        red[threadIdx.x] = sv[lvl]; __syncthreads();
        for (int o = 128; o > 0; o >>= 1) {
            if (threadIdx.x < o) red[threadIdx.x] += red[threadIdx.x + o];
            __syncthreads();
        }
        if (threadIdx.x == 0) g_part[blockIdx.x*3 + lvl] = red[0];
        __syncthreads();
    }
}

__global__ void nash_upd_k(const float* aggl) {
    if (threadIdx.x || blockIdx.x) return;
    double s0 = 0., s1 = 0., s2 = 0.;
    for (int i = 0; i < NREDB; i++) { s0 += g_part[i*3]; s1 += g_part[i*3+1]; s2 += g_part[i*3+2]; }
    float u0 = (float)(-(s0 * (1.0 / (double)BND)));
    float u1 = (float)(-(s1 * (1.0 / (double)BND)));
    float u2 = (float)(-(s2 * (1.0 / (double)BND)));
    float w[3];
    softmax3_f32(aggl[0] + u0, aggl[1] + u1, aggl[2] + u2, w);
    g_w[0] = w[0]; g_w[1] = w[1]; g_w[2] = w[2];
}

// ---------------- residual mixes ----------------
__global__ void comb1_k(const float* __restrict__ x, float* __restrict__ x1) {
    size_t idx = (size_t)blockIdx.x * 256 + threadIdx.x;
    if (idx >= (size_t)BND) return;
    size_t bn = idx / Dd; int d = (int)(idx % Dd);
    int b = (int)(bn / Nn), n = (int)(bn % Nn);
    float ao = g_w[0]*g_Z0[idx]
             + g_w[1]*g_Z1[((size_t)b*(Nn/2) + (n>>1)) * Dd + d]
             + g_w[2]*g_Z2[((size_t)b*(Nn/4) + (n>>2)) * Dd + d];
    x1[idx] = g_P[0]*x[idx] + g_P[1]*ao;
}

__global__ void comb2_k(const float* __restrict__ x1, const float* __restrict__ ffn,
                        float* __restrict__ out) {
    size_t idx = (size_t)blockIdx.x * 256 + threadIdx.x;
    if (idx >= (size_t)BND) return;
    out[idx] = g_P[4]*x1[idx] + g_P[5]*ffn[idx];
}

__global__ void silu_mul_k(const float* __restrict__ g, const float* __restrict__ u,
                           float* __restrict__ h, long long n) {
    long long idx = (long long)blockIdx.x * 256 + threadIdx.x;
    if (idx >= n) return;
    float gv = g[idx];
    float sig = 1.0f / (1.0f + __expf(-gv));
    h[idx] = gv * sig * u[idx];
}

// ---------------- aux loss: fp32 bit-emulation ----------------
__global__ void aux_k(float* out) {
    if (threadIdx.x || blockIdx.x) return;
    float p[3];
    #pragma unroll
    for (int l = 0; l < 3; l++) {
        float w = g_w[l];
        float t = w * 3.0f;
        t = t + 1e-9f;
        float gl = f32_log(t);
        p[l] = w * gl;
    }
    out[BND] = (p[0] + p[1]) + p[2];
}

// ---------------- launcher ----------------
extern "C" void kernel_launch(void* const* d_in, const int* in_sizes, int n_in,
                              void* d_out, int out_size) {
    const float* x    = (const float*)d_in[0];
    const float* nw1  = (const float*)d_in[1];
    const float* nw2  = (const float*)d_in[2];
    const float* Wdec = (const float*)d_in[3];
    const float* Wq   = (const float*)d_in[4];
    const float* Wk   = (const float*)d_in[5];
    const float* Wv   = (const float*)d_in[6];
    const float* Wo   = (const float*)d_in[7];
    const float* aggl = (const float*)d_in[8];
    const float* wg   = (const float*)d_in[9];
    const float* wu   = (const float*)d_in[10];
    const float* wd   = (const float*)d_in[11];
    const float* ml1  = (const float*)d_in[12];
    const float* ml2  = (const float*)d_in[13];
    float* out = (float*)d_out;
    int HID = in_sizes[9] / Dd;          // 2734
    if (HID > HID_MAX) HID = HID_MAX;

    float *xn,*p1,*p2,*sc0,*sc1,*sc2,*q,*k,*v,*ao,*Z0,*Z1,*Z2,*x1,*gg,*gu;
    cudaGetSymbolAddress((void**)&xn,  g_xn);
    cudaGetSymbolAddress((void**)&p1,  g_p1);
    cudaGetSymbolAddress((void**)&p2,  g_p2);
    cudaGetSymbolAddress((void**)&sc0, g_sc0);
    cudaGetSymbolAddress((void**)&sc1, g_sc1);
    cudaGetSymbolAddress((void**)&sc2, g_sc2);
    cudaGetSymbolAddress((void**)&q,   g_q);
    cudaGetSymbolAddress((void**)&k,   g_k);
    cudaGetSymbolAddress((void**)&v,   g_v);
    cudaGetSymbolAddress((void**)&ao,  g_ao);
    cudaGetSymbolAddress((void**)&Z0,  g_Z0);
    cudaGetSymbolAddress((void**)&Z1,  g_Z1);
    cudaGetSymbolAddress((void**)&Z2,  g_Z2);
    cudaGetSymbolAddress((void**)&x1,  g_x1);
    cudaGetSymbolAddress((void**)&gg,  g_gate);
    cudaGetSymbolAddress((void**)&gu,  g_up);

    // convert A (activations) planes; stride = row stride of src
    auto convA = [&](const float* A, int M, int K, int stride, int three) {
        int Kp = (K + 63) & ~63;
        convA_k<<<(M * Kp + 255) / 256, 256>>>(A, M, K, Kp, stride, three);
    };
    // convert B (weights) + run wmma GEMM with current A planes
    auto gemm = [&](const float* B, float* C, int M, int N, int K, int three, int ldc) {
        int Kp = (K + 63) & ~63;
        int Np = (N + 127) & ~127;
        dim3 gb(Np / 32, Kp / 32);
        convB_k<<<gb, dim3(32, 8)>>>(B, K, N, Kp, Np, three);
        dim3 gt(Np / 128, M / 128);
        wgemm_k<<<gt, 256>>>(C, M, ldc, Kp, three ? 6 : 3);
    };

    smalls_k<<<1, 32>>>(aggl, ml1, ml2);

    // rmsnorm + hierarchical decomposition (3-split: feeds Nash Z chain)
    rmsnorm_k<<<Bb*Nn, 256>>>(x, nw1, xn);
    pool_k<<<(Bb*(Nn/2)*Dd + 255)/256, 256>>>(xn, p1, Bb*(Nn/2)*Dd);
    pool_k<<<(Bb*(Nn/4)*Dd + 255)/256, 256>>>(p1, p2, Bb*(Nn/4)*Dd);
    convA(xn, Bb*Nn, Dd, Dd, 1);      gemm(Wdec + 0*Dd*Dd, sc0, Bb*Nn,     Dd, Dd, 1, Dd);
    convA(p1, Bb*(Nn/2), Dd, Dd, 1);  gemm(Wdec + 1*Dd*Dd, sc1, Bb*(Nn/2), Dd, Dd, 1, Dd);
    convA(p2, Bb*(Nn/4), Dd, Dd, 1);  gemm(Wdec + 2*Dd*Dd, sc2, Bb*(Nn/4), Dd, Dd, 1, Dd);

    const float* scs[3] = {sc0, sc1, sc2};
    float*       Zs[3]  = {Z0, Z1, Z2};
    int          nls[3] = {Nn, Nn/2, Nn/4};
    for (int l = 0; l < Lv; l++) {
        int nl = nls[l], M = Bb * nl;
        convA(scs[l], M, Dd, Dd, 1);
        gemm(Wq + (size_t)l*Dd*Dd, q, M, Dd, Dd, 1, Dd);
        gemm(Wk + (size_t)l*Dd*Dd, k, M, Dd, Dd, 1, Dd);
        gemm(Wv,                   v, M, Dd, Dd, 1, Dd);
        fattn_k<<<dim3(nl/64, Hh, Bb), 256>>>(q, k, v, ao, nl);
        convA(ao, M, Dd, Dd, 1);
        gemm(Wo, Zs[l], M, Dd, Dd, 1, Dd);
    }

    // nash best-response (fp64 reductions, fp32-emulated softmax)
    for (int it = 0; it < 3; it++) {
        nash_red_k<<<NREDB, 256>>>();
        nash_upd_k<<<1, 32>>>(aggl);
    }

    comb1_k<<<(BND + 255)/256, 256>>>(x, x1);

    // SwiGLU FFN (2-split; gate/up stored with padded stride HIDP)
    rmsnorm_k<<<Bb*Nn, 256>>>(x1, nw2, xn);
    convA(xn, Bb*Nn, Dd, Dd, 0);
    gemm(wg, gg, Bb*Nn, HID, Dd, 0, HIDP);
    gemm(wu, gu, Bb*Nn, HID, Dd, 0, HIDP);
    long long nh = (long long)Bb*Nn*HIDP;
    silu_mul_k<<<(unsigned)((nh + 255)/256), 256>>>(gg, gu, gg, nh);
    convA(gg, Bb*Nn, HID, HIDP, 0);
    gemm(wd, ao, Bb*Nn, Dd, HID, 0, Dd);

    comb2_k<<<(BND + 255)/256, 256>>>(x1, ao, out);
    if (out_size > BND) aux_k<<<1, 32>>>(out);
}

// round 7
// speedup vs baseline: 2.3103x; 1.3759x over previous
#include <cuda_runtime.h>
#include <cuda_fp16.h>
#include <mma.h>
#include <math.h>
#include <stdint.h>

// ---------------- problem constants ----------------
#define Bb   2
#define Nn   2048
#define Dd   1024
#define Hh   16
#define DHh  64
#define Lv   3
#define BND  (Bb*Nn*Dd)          // 4,194,304 = 2^22
#define HID_MAX 2816
#define NREDB 1024
#define APLANE (4096*2752)
#define BPLANE (5504*1024 + 2048)

// ---------------- scratch ----------------
__device__ float g_xn  [4096*1024];
__device__ float g_p1  [2048*1024];
__device__ float g_p2  [1024*1024];
__device__ float g_sc0 [4096*1024];
__device__ float g_sc1 [2048*1024];
__device__ float g_sc2 [1024*1024];
__device__ float g_qkv [4096*3072];
__device__ float g_ao  [4096*1024];
__device__ float g_Z0  [4096*1024];
__device__ float g_Z1  [2048*1024];
__device__ float g_Z2  [1024*1024];
__device__ float g_x1  [4096*1024];
__device__ float g_gu  [4096*5504];     // fused gate|up GEMM output
__device__ float g_h   [4096*2734];     // silu(gate)*up, compact
__device__ float  g_w  [4];
__device__ float  g_P  [8];
__device__ double g_part[NREDB*3];
// fp16 split planes (h + residual scaled by 2^11)
__device__ __align__(128) __half g_Ah[APLANE];
__device__ __align__(128) __half g_Am[APLANE];
__device__ __align__(128) __half g_Bh[BPLANE];
__device__ __align__(128) __half g_Bm[BPLANE];

// correctly-rounded fp32 exp/log via fp64 (immune to fast-math)
__device__ __forceinline__ float f32_exp(float x) { return (float)exp((double)x); }
__device__ __forceinline__ float f32_log(float x) { return (float)log((double)x); }

__device__ __forceinline__ void softmax3_f32(float z0, float z1, float z2, float* w) {
    float m = fmaxf(z0, fmaxf(z1, z2));
    float e0 = f32_exp(z0 - m), e1 = f32_exp(z1 - m), e2 = f32_exp(z2 - m);
    float s = (e0 + e1) + e2;
    w[0] = e0 / s; w[1] = e1 / s; w[2] = e2 / s;
}

// ---------------- split conversion: activations [M,K] -> planes [M,Kp] ------
__global__ void convA_k(const float* __restrict__ src, int M, int K, int Kp, int stride) {
    int idx = blockIdx.x * 256 + threadIdx.x;
    if (idx >= M * Kp) return;
    int r = idx / Kp, c = idx % Kp;
    float x = (c < K) ? src[(size_t)r * stride + c] : 0.f;
    __half hh = __float2half(x);
    float r1 = x - __half2float(hh);
    g_Ah[idx] = hh;
    g_Am[idx] = __float2half(r1 * 2048.0f);
}

// weights [K,N] fp32 -> transposed planes rows [n0+0 .. n0+ceil32(N)) of [*,Kp]
__global__ void convB_k(const float* __restrict__ src, int K, int N, int Kp, int n0) {
    __shared__ float t[32][33];
    int kt = blockIdx.y * 32, nt = blockIdx.x * 32;
    int tx = threadIdx.x, ty = threadIdx.y;   // 32 x 8
    for (int i = ty; i < 32; i += 8) {
        int kk = kt + i, nn = nt + tx;
        t[i][tx] = (kk < K && nn < N) ? src[(size_t)kk * N + nn] : 0.f;
    }
    __syncthreads();
    for (int i = ty; i < 32; i += 8) {
        int nn = nt + i, kk = kt + tx;
        float x = t[tx][i];
        size_t o = (size_t)(n0 + nn) * Kp + kk;
        __half hh = __float2half(x);
        float r1 = x - __half2float(hh);
        g_Bh[o] = hh;
        g_Bm[o] = __float2half(r1 * 2048.0f);
    }
}

// ---------------- wmma fp16 2-split GEMM: C[M,*] = A @ B^T ------------------
// 3 plane-pairs: hh -> acc0; hm, mh -> acc1 (scaled 2^11); C = acc0 + acc1/2048.
// grid (Np/128, M/128), 256 threads, warp tile 32x64.
__global__ void __launch_bounds__(256)
wgemm_k(float* __restrict__ C, int M, int ldc, int Kp) {
    using namespace nvcuda;
    __shared__ __half As[2][128][40];
    __shared__ __half Bs[2][128][40];
    int tid = threadIdx.x, wid = tid >> 5;
    int bm = blockIdx.y * 128, bn = blockIdx.x * 128;
    int wm = wid & 3, wn = wid >> 2;          // 4 m-tiles x 2 n-tiles
    int row = tid >> 1, cq = (tid & 1) * 16;
    int kchunks = Kp >> 5;
    int total = 3 * kchunks;

    wmma::fragment<wmma::accumulator, 16, 16, 16, float> acc0[2][4], acc1[2][4];
    #pragma unroll
    for (int i = 0; i < 2; i++)
        #pragma unroll
        for (int j = 0; j < 4; j++) {
            wmma::fill_fragment(acc0[i][j], 0.f);
            wmma::fill_fragment(acc1[i][j], 0.f);
        }

    // preload chunk 0 (pair hh)
    {
        const __half* ar = g_Ah + (size_t)(bm + row) * Kp + cq;
        const __half* br = g_Bh + (size_t)(bn + row) * Kp + cq;
        *(uint4*)&As[0][row][cq]     = *(const uint4*)ar;
        *(uint4*)&As[0][row][cq + 8] = *(const uint4*)(ar + 8);
        *(uint4*)&Bs[0][row][cq]     = *(const uint4*)br;
        *(uint4*)&Bs[0][row][cq + 8] = *(const uint4*)(br + 8);
    }
    __syncthreads();

    for (int c = 0; c < total; c++) {
        int cur = c & 1;
        uint4 ra0, ra1, rb0, rb1;
        bool more = (c + 1 < total);
        if (more) {
            int pr = (c + 1) / kchunks, kc = ((c + 1) % kchunks) * 32;
            const __half* Ag = (pr == 2) ? g_Am : g_Ah;
            const __half* Bg = (pr == 1) ? g_Bm : g_Bh;
            const __half* ar = Ag + (size_t)(bm + row) * Kp + kc + cq;
            const __half* br = Bg + (size_t)(bn + row) * Kp + kc + cq;
            ra0 = *(const uint4*)ar; ra1 = *(const uint4*)(ar + 8);
            rb0 = *(const uint4*)br; rb1 = *(const uint4*)(br + 8);
        }
        int grp = (c >= kchunks);   // pair 0 -> acc0; pairs 1,2 -> acc1
        #pragma unroll
        for (int ks = 0; ks < 2; ks++) {
            wmma::fragment<wmma::matrix_a, 16, 16, 16, __half, wmma::row_major> af[2];
            wmma::fragment<wmma::matrix_b, 16, 16, 16, __half, wmma::col_major> bf[4];
            wmma::load_matrix_sync(af[0], &As[cur][wm * 32][ks * 16], 40);
            wmma::load_matrix_sync(af[1], &As[cur][wm * 32 + 16][ks * 16], 40);
            #pragma unroll
            for (int j = 0; j < 4; j++)
                wmma::load_matrix_sync(bf[j], &Bs[cur][wn * 64 + j * 16][ks * 16], 40);
            if (grp == 0) {
                #pragma unroll
                for (int i = 0; i < 2; i++)
                    #pragma unroll
                    for (int j = 0; j < 4; j++)
                        wmma::mma_sync(acc0[i][j], af[i], bf[j], acc0[i][j]);
            } else {
                #pragma unroll
                for (int i = 0; i < 2; i++)
                    #pragma unroll
                    for (int j = 0; j < 4; j++)
                        wmma::mma_sync(acc1[i][j], af[i], bf[j], acc1[i][j]);
            }
        }
        if (more) {
            int nxt = cur ^ 1;
            *(uint4*)&As[nxt][row][cq]     = ra0;
            *(uint4*)&As[nxt][row][cq + 8] = ra1;
            *(uint4*)&Bs[nxt][row][cq]     = rb0;
            *(uint4*)&Bs[nxt][row][cq + 8] = rb1;
        }
        __syncthreads();
    }
    const float inv = 1.0f / 2048.0f;
    #pragma unroll
    for (int i = 0; i < 2; i++)
        #pragma unroll
        for (int j = 0; j < 4; j++) {
            #pragma unroll
            for (int e = 0; e < acc0[i][j].num_elements; e++)
                acc0[i][j].x[e] += acc1[i][j].x[e] * inv;
            int r = bm + wm * 32 + i * 16, cc = bn + wn * 64 + j * 16;
            wmma::store_matrix_sync(&C[(size_t)r * ldc + cc], acc0[i][j], ldc,
                                    wmma::mem_row_major);
        }
}

// ---------------- rmsnorm ----------------
__global__ void rmsnorm_k(const float* __restrict__ x, const float* __restrict__ w,
                          float* __restrict__ y) {
    int row = blockIdx.x;
    const float* xr = x + (size_t)row * Dd;
    float s = 0.f;
    for (int i = threadIdx.x; i < Dd; i += 256) { float v = xr[i]; s += v * v; }
    __shared__ float red[256];
    red[threadIdx.x] = s; __syncthreads();
    for (int o = 128; o > 0; o >>= 1) {
        if (threadIdx.x < o) red[threadIdx.x] += red[threadIdx.x + o];
        __syncthreads();
    }
    float r = rsqrtf(red[0] / (float)Dd + 1e-6f);
    float* yr = y + (size_t)row * Dd;
    for (int i = threadIdx.x; i < Dd; i += 256) yr[i] = xr[i] * w[i] * r;
}

// ---------------- avg-pool by 2 ----------------
__global__ void pool_k(const float* __restrict__ in, float* __restrict__ out, int noutD) {
    int idx = blockIdx.x * 256 + threadIdx.x;
    if (idx >= noutD) return;
    int row = idx / Dd, d = idx % Dd;
    out[idx] = 0.5f * (in[(size_t)(2*row) * Dd + d] + in[(size_t)(2*row+1) * Dd + d]);
}

// ---------------- flash attention (fp32), q/k/v share stride ld -------------
__global__ void __launch_bounds__(256, 2)
fattn_k(const float* __restrict__ q, const float* __restrict__ k,
        const float* __restrict__ v, float* __restrict__ o, int nl, int ld) {
    __shared__ float Qs[64][68];
    __shared__ float Kt[64][36];
    __shared__ float Vs[32][68];
    __shared__ float Ps[64][36];
    int qt = blockIdx.x, h = blockIdx.y, b = blockIdx.z;
    int tid = threadIdx.x;
    int tx = tid & 15, ty = tid >> 4;
    const size_t base  = (size_t)b * nl * ld + (size_t)h * DHh;
    const size_t obase = (size_t)b * nl * Dd + (size_t)h * DHh;
    int q0 = qt * 64;
    {
        int qr = tid >> 2, qc0 = (tid & 3) * 16;
        #pragma unroll
        for (int j = 0; j < 4; j++) {
            float4 t4 = *(const float4*)&q[base + (size_t)(q0 + qr) * ld + qc0 + j * 4];
            t4.x *= 0.125f; t4.y *= 0.125f; t4.z *= 0.125f; t4.w *= 0.125f;
            *(float4*)&Qs[qr][qc0 + j * 4] = t4;
        }
    }
    float O[4][4] = {};
    float m[4], l[4];
    #pragma unroll
    for (int i = 0; i < 4; i++) { m[i] = -1e30f; l[i] = 0.f; }
    int nkt = 2 * qt + 2;
    for (int kt = 0; kt < nkt; kt++) {
        int k0 = kt * 32;
        {
            int kr = tid >> 3, dc0 = (tid & 7) * 8;
            #pragma unroll
            for (int jj = 0; jj < 8; jj++)
                Kt[dc0 + jj][kr] = k[base + (size_t)(k0 + kr) * ld + dc0 + jj];
            int vr = (kr < 32) ? kr : kr - 32;
            #pragma unroll
            for (int j = 0; j < 2; j++)
                *(float4*)&Vs[vr][dc0 + j * 4] =
                    *(const float4*)&v[base + (size_t)(k0 + vr) * ld + dc0 + j * 4];
        }
        __syncthreads();
        float S[4][2] = {};
        #pragma unroll 4
        for (int d = 0; d < 64; d++) {
            float kv0 = Kt[d][tx * 2], kv1 = Kt[d][tx * 2 + 1];
            #pragma unroll
            for (int i = 0; i < 4; i++) {
                float qv = Qs[ty * 4 + i][d];
                S[i][0] += qv * kv0;
                S[i][1] += qv * kv1;
            }
        }
        if (k0 + 31 > q0) {
            #pragma unroll
            for (int i = 0; i < 4; i++) {
                int qg = q0 + ty * 4 + i;
                #pragma unroll
                for (int j = 0; j < 2; j++)
                    if (k0 + tx * 2 + j > qg) S[i][j] = -1e30f;
            }
        }
        #pragma unroll
        for (int i = 0; i < 4; i++) {
            float rm = fmaxf(S[i][0], S[i][1]);
            #pragma unroll
            for (int off = 8; off > 0; off >>= 1)
                rm = fmaxf(rm, __shfl_xor_sync(0xffffffffu, rm, off));
            float mn = fmaxf(m[i], rm);
            float sc = __expf(m[i] - mn);
            float e0 = __expf(S[i][0] - mn);
            float e1 = __expf(S[i][1] - mn);
            S[i][0] = e0; S[i][1] = e1;
            float rs = e0 + e1;
            #pragma unroll
            for (int off = 8; off > 0; off >>= 1)
                rs += __shfl_xor_sync(0xffffffffu, rs, off);
            l[i] = l[i] * sc + rs;
            m[i] = mn;
            #pragma unroll
            for (int j = 0; j < 4; j++) O[i][j] *= sc;
        }
        #pragma unroll
        for (int i = 0; i < 4; i++) {
            Ps[ty * 4 + i][tx * 2]     = S[i][0];
            Ps[ty * 4 + i][tx * 2 + 1] = S[i][1];
        }
        __syncthreads();
        #pragma unroll 4
        for (int c = 0; c < 32; c++) {
            float4 vv = *(const float4*)&Vs[c][tx * 4];
            #pragma unroll
            for (int i = 0; i < 4; i++) {
                float pv = Ps[ty * 4 + i][c];
                O[i][0] += pv * vv.x;
                O[i][1] += pv * vv.y;
                O[i][2] += pv * vv.z;
                O[i][3] += pv * vv.w;
            }
        }
        __syncthreads();
    }
    #pragma unroll
    for (int i = 0; i < 4; i++) {
        float inv = 1.0f / l[i];
        size_t orow = obase + (size_t)(q0 + ty * 4 + i) * Dd + tx * 4;
        #pragma unroll
        for (int j = 0; j < 4; j++) o[orow + j] = O[i][j] * inv;
    }
}

// ---------------- small scalar kernels ----------------
__global__ void smalls_k(const float* aggl, const float* ml1, const float* ml2) {
    if (threadIdx.x || blockIdx.x) return;
    for (int s = 0; s < 2; s++) {
        const float* ml = s ? ml2 : ml1;
        float M0 = f32_exp(ml[0]), M1 = f32_exp(ml[1]), M2 = f32_exp(ml[2]), M3 = f32_exp(ml[3]);
        for (int it = 0; it < 10; it++) {
            float r0 = M0 + M1, r1 = M2 + M3;
            M0 /= r0; M1 /= r0; M2 /= r1; M3 /= r1;
            float c0 = M0 + M2, c1 = M1 + M3;
            M0 /= c0; M2 /= c0; M1 /= c1; M3 /= c1;
        }
        g_P[s*4+0] = M0; g_P[s*4+1] = M1; g_P[s*4+2] = M2; g_P[s*4+3] = M3;
    }
    float w[3];
    softmax3_f32(aggl[0], aggl[1], aggl[2], w);
    g_w[0] = w[0]; g_w[1] = w[1]; g_w[2] = w[2];
}

// ---------------- nash: fp64 deterministic reductions ----------------
__global__ void nash_red_k() {
    double w0 = (double)g_w[0], w1 = (double)g_w[1], w2 = (double)g_w[2];
    double s0 = 0., s1 = 0., s2 = 0.;
    for (size_t idx = (size_t)blockIdx.x * 256 + threadIdx.x; idx < (size_t)BND;
         idx += (size_t)NREDB * 256) {
        size_t bn = idx / Dd; int d = (int)(idx % Dd);
        int b = (int)(bn / Nn), n = (int)(bn % Nn);
        double z0 = (double)g_Z0[idx];
        double z1 = (double)g_Z1[((size_t)b*(Nn/2) + (n>>1)) * Dd + d];
        double z2 = (double)g_Z2[((size_t)b*(Nn/4) + (n>>2)) * Dd + d];
        double yb = w0*z0 + w1*z1 + w2*z2;
        double d0 = z0-yb, d1 = z1-yb, d2 = z2-yb;
        s0 += d0*d0; s1 += d1*d1; s2 += d2*d2;
    }
    __shared__ double red[256];
    double sv[3] = {s0, s1, s2};
    for (int lvl = 0; lvl < 3; lvl++) {
        red[threadIdx.x] = sv[lvl]; __syncthreads();
        for (int o = 128; o > 0; o >>= 1) {
            if (threadIdx.x < o) red[threadIdx.x] += red[threadIdx.x + o];
            __syncthreads();
        }
        if (threadIdx.x == 0) g_part[blockIdx.x*3 + lvl] = red[0];
        __syncthreads();
    }
}

__global__ void nash_upd_k(const float* aggl) {
    if (threadIdx.x || blockIdx.x) return;
    double s0 = 0., s1 = 0., s2 = 0.;
    for (int i = 0; i < NREDB; i++) { s0 += g_part[i*3]; s1 += g_part[i*3+1]; s2 += g_part[i*3+2]; }
    float u0 = (float)(-(s0 * (1.0 / (double)BND)));
    float u1 = (float)(-(s1 * (1.0 / (double)BND)));
    float u2 = (float)(-(s2 * (1.0 / (double)BND)));
    float w[3];
    softmax3_f32(aggl[0] + u0, aggl[1] + u1, aggl[2] + u2, w);
    g_w[0] = w[0]; g_w[1] = w[1]; g_w[2] = w[2];
}

// ---------------- residual mixes ----------------
__global__ void comb1_k(const float* __restrict__ x, float* __restrict__ x1) {
    size_t idx = (size_t)blockIdx.x * 256 + threadIdx.x;
    if (idx >= (size_t)BND) return;
    size_t bn = idx / Dd; int d = (int)(idx % Dd);
    int b = (int)(bn / Nn), n = (int)(bn % Nn);
    float ao = g_w[0]*g_Z0[idx]
             + g_w[1]*g_Z1[((size_t)b*(Nn/2) + (n>>1)) * Dd + d]
             + g_w[2]*g_Z2[((size_t)b*(Nn/4) + (n>>2)) * Dd + d];
    x1[idx] = g_P[0]*x[idx] + g_P[1]*ao;
}

__global__ void comb2_k(const float* __restrict__ x1, const float* __restrict__ ffn,
                        float* __restrict__ out) {
    size_t idx = (size_t)blockIdx.x * 256 + threadIdx.x;
    if (idx >= (size_t)BND) return;
    out[idx] = g_P[4]*x1[idx] + g_P[5]*ffn[idx];
}

// silu(gate)*up from fused [M, 5504] buffer -> compact [M, HID]
__global__ void silu2_k(const float* __restrict__ guf, float* __restrict__ h,
                        int HIDv, long long n) {
    long long idx = (long long)blockIdx.x * 256 + threadIdx.x;
    if (idx >= n) return;
    int r = (int)(idx / HIDv), j = (int)(idx % HIDv);
    float gv = guf[(size_t)r * 5504 + j];
    float uv = guf[(size_t)r * 5504 + 2752 + j];
    float sig = 1.0f / (1.0f + __expf(-gv));
    h[idx] = gv * sig * uv;
}

// ---------------- aux loss: fp32 bit-emulation ----------------
__global__ void aux_k(float* out) {
    if (threadIdx.x || blockIdx.x) return;
    float p[3];
    #pragma unroll
    for (int l = 0; l < 3; l++) {
        float w = g_w[l];
        float t = w * 3.0f;
        t = t + 1e-9f;
        float gl = f32_log(t);
        p[l] = w * gl;
    }
    out[BND] = (p[0] + p[1]) + p[2];
}

// ---------------- launcher ----------------
extern "C" void kernel_launch(void* const* d_in, const int* in_sizes, int n_in,
                              void* d_out, int out_size) {
    const float* x    = (const float*)d_in[0];
    const float* nw1  = (const float*)d_in[1];
    const float* nw2  = (const float*)d_in[2];
    const float* Wdec = (const float*)d_in[3];
    const float* Wq   = (const float*)d_in[4];
    const float* Wk   = (const float*)d_in[5];
    const float* Wv   = (const float*)d_in[6];
    const float* Wo   = (const float*)d_in[7];
    const float* aggl = (const float*)d_in[8];
    const float* wg   = (const float*)d_in[9];
    const float* wu   = (const float*)d_in[10];
    const float* wd   = (const float*)d_in[11];
    const float* ml1  = (const float*)d_in[12];
    const float* ml2  = (const float*)d_in[13];
    float* out = (float*)d_out;
    int HID = in_sizes[9] / Dd;          // 2734
    if (HID > HID_MAX) HID = HID_MAX;

    float *xn,*p1,*p2,*sc0,*sc1,*sc2,*qkv,*ao,*Z0,*Z1,*Z2,*x1,*gu,*hbuf;
    cudaGetSymbolAddress((void**)&xn,  g_xn);
    cudaGetSymbolAddress((void**)&p1,  g_p1);
    cudaGetSymbolAddress((void**)&p2,  g_p2);
    cudaGetSymbolAddress((void**)&sc0, g_sc0);
    cudaGetSymbolAddress((void**)&sc1, g_sc1);
    cudaGetSymbolAddress((void**)&sc2, g_sc2);
    cudaGetSymbolAddress((void**)&qkv, g_qkv);
    cudaGetSymbolAddress((void**)&ao,  g_ao);
    cudaGetSymbolAddress((void**)&Z0,  g_Z0);
    cudaGetSymbolAddress((void**)&Z1,  g_Z1);
    cudaGetSymbolAddress((void**)&Z2,  g_Z2);
    cudaGetSymbolAddress((void**)&x1,  g_x1);
    cudaGetSymbolAddress((void**)&gu,  g_gu);
    cudaGetSymbolAddress((void**)&hbuf,g_h);

    auto convA = [&](const float* A, int M, int K, int stride) {
        int Kp = (K + 63) & ~63;
        convA_k<<<(M * Kp + 255) / 256, 256>>>(A, M, K, Kp, stride);
    };
    auto convB = [&](const float* B, int K, int N, int n0) {
        int Kp = (K + 63) & ~63;
        dim3 gb((N + 31) / 32, Kp / 32);
        convB_k<<<gb, dim3(32, 8)>>>(B, K, N, Kp, n0);
    };
    auto run = [&](float* C, int M, int Np, int K, int ldc) {
        int Kp = (K + 63) & ~63;
        dim3 gt(Np / 128, M / 128);
        wgemm_k<<<gt, 256>>>(C, M, ldc, Kp);
    };

    // order chosen so wgemm_k is app-launch index 3 (ncu capture slot)
    rmsnorm_k<<<Bb*Nn, 256>>>(x, nw1, xn);                       // 0
    convA(xn, Bb*Nn, Dd, Dd);                                    // 1
    convB(Wdec + 0*Dd*Dd, Dd, Dd, 0);                            // 2
    run(sc0, Bb*Nn, 1024, Dd, Dd);                               // 3 <- profiled
    pool_k<<<(Bb*(Nn/2)*Dd + 255)/256, 256>>>(xn, p1, Bb*(Nn/2)*Dd);
    pool_k<<<(Bb*(Nn/4)*Dd + 255)/256, 256>>>(p1, p2, Bb*(Nn/4)*Dd);

    // level 0 QKV reuses the xn planes already converted
    convB(Wq + 0, Dd, Dd, 0);
    convB(Wk + 0, Dd, Dd, 1024);
    convB(Wv,     Dd, Dd, 2048);
    // (A planes currently hold xn, but QKV needs sc0 -> convert now)
    convA(sc0, Bb*Nn, Dd, Dd);
    run(qkv, Bb*Nn, 3072, Dd, 3072);
    fattn_k<<<dim3(Nn/64, Hh, Bb), 256>>>(qkv, qkv+1024, qkv+2048, ao, Nn, 3072);
    convA(ao, Bb*Nn, Dd, Dd);
    convB(Wo, Dd, Dd, 0);
    run(Z0, Bb*Nn, 1024, Dd, Dd);

    // levels 1,2
    {
        const float* ps[2]  = {p1, p2};
        float*       scp[2] = {sc1, sc2};
        float*       Zp[2]  = {Z1, Z2};
        for (int l = 1; l < Lv; l++) {
            int nl = (l == 1) ? Nn/2 : Nn/4, M = Bb * nl;
            convA(ps[l-1], M, Dd, Dd);
            convB(Wdec + (size_t)l*Dd*Dd, Dd, Dd, 0);
            run(scp[l-1], M, 1024, Dd, Dd);
            convA(scp[l-1], M, Dd, Dd);
            convB(Wq + (size_t)l*Dd*Dd, Dd, Dd, 0);
            convB(Wk + (size_t)l*Dd*Dd, Dd, Dd, 1024);
            convB(Wv,                   Dd, Dd, 2048);
            run(qkv, M, 3072, Dd, 3072);
            fattn_k<<<dim3(nl/64, Hh, Bb), 256>>>(qkv, qkv+1024, qkv+2048, ao, nl, 3072);
            convA(ao, M, Dd, Dd);
            convB(Wo, Dd, Dd, 0);
            run(Zp[l-1], M, 1024, Dd, Dd);
        }
    }

    // sinkhorn + nash init, then best-response iterations
    smalls_k<<<1, 32>>>(aggl, ml1, ml2);
    for (int it = 0; it < 3; it++) {
        nash_red_k<<<NREDB, 256>>>();
        nash_upd_k<<<1, 32>>>(aggl);
    }

    comb1_k<<<(BND + 255)/256, 256>>>(x, x1);

    // SwiGLU FFN: fused gate|up GEMM (N sections at 0 and 2752), then down
    rmsnorm_k<<<Bb*Nn, 256>>>(x1, nw2, xn);
    convA(xn, Bb*Nn, Dd, Dd);
    convB(wg, Dd, HID, 0);
    convB(wu, Dd, HID, 2752);
    run(gu, Bb*Nn, 5504, Dd, 5504);
    long long nh = (long long)Bb*Nn*HID;
    silu2_k<<<(unsigned)((nh + 255)/256), 256>>>(gu, hbuf, HID, nh);
    convA(hbuf, Bb*Nn, HID, HID);
    convB(wd, HID, Dd, 0);
    run(ao, Bb*Nn, 1024, HID, Dd);

    comb2_k<<<(BND + 255)/256, 256>>>(x1, ao, out);
    if (out_size > BND) aux_k<<<1, 32>>>(out);
}

// round 8
// speedup vs baseline: 3.2653x; 1.4134x over previous
#include <cuda_runtime.h>
#include <cuda_fp16.h>
#include <mma.h>
#include <math.h>
#include <stdint.h>

// ---------------- problem constants ----------------
#define Bb   2
#define Nn   2048
#define Dd   1024
#define Hh   16
#define DHh  64
#define Lv   3
#define BND  (Bb*Nn*Dd)          // 4,194,304 = 2^22
#define HID_MAX 2816
#define NREDB 1024
#define APLANE (4096*2752)
#define BPLANE (5504*1024 + 2048)

// ---------------- scratch ----------------
__device__ float g_xn  [4096*1024];
__device__ float g_p1  [2048*1024];
__device__ float g_p2  [1024*1024];
__device__ float g_sc0 [4096*1024];
__device__ float g_sc1 [2048*1024];
__device__ float g_sc2 [1024*1024];
__device__ float g_qkv [4096*3072];
__device__ float g_ao  [4096*1024];
__device__ float g_Z0  [4096*1024];
__device__ float g_Z1  [2048*1024];
__device__ float g_Z2  [1024*1024];
__device__ float g_x1  [4096*1024];
__device__ float g_gu  [4096*5504];
__device__ float g_h   [4096*2734];
__device__ float  g_w  [4];
__device__ float  g_P  [8];
__device__ double g_part[NREDB*3];
// fp16 split planes (h + residual scaled by 2^11)
__device__ __align__(128) __half g_Ah[APLANE];
__device__ __align__(128) __half g_Am[APLANE];
__device__ __align__(128) __half g_Bh[BPLANE];
__device__ __align__(128) __half g_Bm[BPLANE];

// correctly-rounded fp32 exp/log via fp64 (immune to fast-math)
__device__ __forceinline__ float f32_exp(float x) { return (float)exp((double)x); }
__device__ __forceinline__ float f32_log(float x) { return (float)log((double)x); }

__device__ __forceinline__ void softmax3_f32(float z0, float z1, float z2, float* w) {
    float m = fmaxf(z0, fmaxf(z1, z2));
    float e0 = f32_exp(z0 - m), e1 = f32_exp(z1 - m), e2 = f32_exp(z2 - m);
    float s = (e0 + e1) + e2;
    w[0] = e0 / s; w[1] = e1 / s; w[2] = e2 / s;
}

__device__ __forceinline__ uint32_t smem_u32(const void* p) {
    uint32_t a;
    asm("{ .reg .u64 t; cvta.to.shared.u64 t, %1; cvt.u32.u64 %0, t; }" : "=r"(a) : "l"(p));
    return a;
}
#define CP16(sa, ga) \
    asm volatile("cp.async.cg.shared.global [%0], [%1], 16;" :: "r"(sa), "l"(ga))
#define CP_COMMIT() asm volatile("cp.async.commit_group;" ::: "memory")
#define CP_WAIT0()  asm volatile("cp.async.wait_group 0;" ::: "memory")

// ---------------- split conversion: activations [M,K] -> planes [M,Kp] ------
__global__ void convA_k(const float* __restrict__ src, int M, int K, int Kp,
                        int stride, int wantm) {
    int idx = blockIdx.x * 256 + threadIdx.x;
    if (idx >= M * Kp) return;
    int r = idx / Kp, c = idx % Kp;
    float x = (c < K) ? src[(size_t)r * stride + c] : 0.f;
    __half hh = __float2half(x);
    g_Ah[idx] = hh;
    if (wantm) g_Am[idx] = __float2half((x - __half2float(hh)) * 2048.0f);
}

// weights [K,N] fp32 -> transposed planes rows [n0 .. n0+ceil32(N)) of [*,Kp]
__global__ void convB_k(const float* __restrict__ src, int K, int N, int Kp,
                        int n0, int wantm) {
    __shared__ float t[32][33];
    int kt = blockIdx.y * 32, nt = blockIdx.x * 32;
    int tx = threadIdx.x, ty = threadIdx.y;   // 32 x 8
    for (int i = ty; i < 32; i += 8) {
        int kk = kt + i, nn = nt + tx;
        t[i][tx] = (kk < K && nn < N) ? src[(size_t)kk * N + nn] : 0.f;
    }
    __syncthreads();
    for (int i = ty; i < 32; i += 8) {
        int nn = nt + i, kk = kt + tx;
        float x = t[tx][i];
        size_t o = (size_t)(n0 + nn) * Kp + kk;
        __half hh = __float2half(x);
        g_Bh[o] = hh;
        if (wantm) g_Bm[o] = __float2half((x - __half2float(hh)) * 2048.0f);
    }
}

// ---------------- wmma fp16 split GEMM: C[M,*] = A @ B^T --------------------
// npairs=3: chunks [Am*Bh][Ah*Bm] (scaled 2^11) -> rescale acc /2048 -> [Ah*Bh]
// npairs=1: [Ah*Bh] only.
// grid (Np/128, M/128), 256 threads, warp tile 32x64, cp.async double buffer.
__global__ void __launch_bounds__(256, 2)
wgemm_k(float* __restrict__ C, int M, int ldc, int Kp, int npairs) {
    using namespace nvcuda;
    extern __shared__ __half sm[];   // As: [2][128][40] halfs; Bs at +10240 halfs
    int tid = threadIdx.x, wid = tid >> 5;
    int bm = blockIdx.y * 128, bn = blockIdx.x * 128;
    int wm = wid & 3, wn = wid >> 2;
    int row = tid >> 1, cq = (tid & 1) * 16;
    int kchunks = Kp >> 5;
    int total = npairs * kchunks;
    int resc = (npairs == 3) ? 2 * kchunks - 1 : -1;
    uint32_t smb = smem_u32(sm);

    wmma::fragment<wmma::accumulator, 16, 16, 16, float> acc[2][4];
    #pragma unroll
    for (int i = 0; i < 2; i++)
        #pragma unroll
        for (int j = 0; j < 4; j++) wmma::fill_fragment(acc[i][j], 0.f);

    auto issue = [&](int c1, int buf) {
        int pr = c1 / kchunks, kc = (c1 % kchunks) * 32;
        const __half* Ag = (npairs == 3 && pr == 0) ? g_Am : g_Ah;
        const __half* Bg = (npairs == 3 && pr == 1) ? g_Bm : g_Bh;
        const __half* ar = Ag + (size_t)(bm + row) * Kp + kc + cq;
        const __half* br = Bg + (size_t)(bn + row) * Kp + kc + cq;
        uint32_t sa = smb + buf * 10240 + (row * 40 + cq) * 2;
        uint32_t sb = smb + 20480 + buf * 10240 + (row * 40 + cq) * 2;
        CP16(sa, ar);      CP16(sa + 16, ar + 8);
        CP16(sb, br);      CP16(sb + 16, br + 8);
    };

    issue(0, 0); CP_COMMIT(); CP_WAIT0();
    __syncthreads();

    for (int c = 0; c < total; c++) {
        int cur = c & 1;
        bool more = (c + 1 < total);
        if (more) { issue(c + 1, cur ^ 1); CP_COMMIT(); }
        #pragma unroll
        for (int ks = 0; ks < 2; ks++) {
            wmma::fragment<wmma::matrix_a, 16, 16, 16, __half, wmma::row_major> af0, af1;
            wmma::load_matrix_sync(af0, &sm[cur * 5120 + (wm * 32) * 40 + ks * 16], 40);
            wmma::load_matrix_sync(af1, &sm[cur * 5120 + (wm * 32 + 16) * 40 + ks * 16], 40);
            #pragma unroll
            for (int j = 0; j < 4; j++) {
                wmma::fragment<wmma::matrix_b, 16, 16, 16, __half, wmma::col_major> bf;
                wmma::load_matrix_sync(bf,
                    &sm[10240 + cur * 5120 + (wn * 64 + j * 16) * 40 + ks * 16], 40);
                wmma::mma_sync(acc[0][j], af0, bf, acc[0][j]);
                wmma::mma_sync(acc[1][j], af1, bf, acc[1][j]);
            }
        }
        if (c == resc) {
            const float inv = 1.0f / 2048.0f;
            #pragma unroll
            for (int i = 0; i < 2; i++)
                #pragma unroll
                for (int j = 0; j < 4; j++)
                    #pragma unroll
                    for (int e = 0; e < acc[i][j].num_elements; e++)
                        acc[i][j].x[e] *= inv;
        }
        if (more) CP_WAIT0();
        __syncthreads();
    }
    #pragma unroll
    for (int i = 0; i < 2; i++)
        #pragma unroll
        for (int j = 0; j < 4; j++) {
            int r = bm + wm * 32 + i * 16, cc = bn + wn * 64 + j * 16;
            wmma::store_matrix_sync(&C[(size_t)r * ldc + cc], acc[i][j], ldc,
                                    wmma::mem_row_major);
        }
}

// ---------------- rmsnorm ----------------
__global__ void rmsnorm_k(const float* __restrict__ x, const float* __restrict__ w,
                          float* __restrict__ y) {
    int row = blockIdx.x;
    const float* xr = x + (size_t)row * Dd;
    float s = 0.f;
    for (int i = threadIdx.x; i < Dd; i += 256) { float v = xr[i]; s += v * v; }
    __shared__ float red[256];
    red[threadIdx.x] = s; __syncthreads();
    for (int o = 128; o > 0; o >>= 1) {
        if (threadIdx.x < o) red[threadIdx.x] += red[threadIdx.x + o];
        __syncthreads();
    }
    float r = rsqrtf(red[0] / (float)Dd + 1e-6f);
    float* yr = y + (size_t)row * Dd;
    for (int i = threadIdx.x; i < Dd; i += 256) yr[i] = xr[i] * w[i] * r;
}

// ---------------- avg-pool by 2 ----------------
__global__ void pool_k(const float* __restrict__ in, float* __restrict__ out, int noutD) {
    int idx = blockIdx.x * 256 + threadIdx.x;
    if (idx >= noutD) return;
    int row = idx / Dd, d = idx % Dd;
    out[idx] = 0.5f * (in[(size_t)(2*row) * Dd + d] + in[(size_t)(2*row+1) * Dd + d]);
}

// ---------------- flash attention (fp32), q/k/v share stride ld -------------
__global__ void __launch_bounds__(256, 2)
fattn_k(const float* __restrict__ q, const float* __restrict__ k,
        const float* __restrict__ v, float* __restrict__ o, int nl, int ld) {
    __shared__ float Qs[64][68];
    __shared__ float Kt[64][36];
    __shared__ float Vs[32][68];
    __shared__ float Ps[64][36];
    int qt = blockIdx.x, h = blockIdx.y, b = blockIdx.z;
    int tid = threadIdx.x;
    int tx = tid & 15, ty = tid >> 4;
    const size_t base  = (size_t)b * nl * ld + (size_t)h * DHh;
    const size_t obase = (size_t)b * nl * Dd + (size_t)h * DHh;
    int q0 = qt * 64;
    {
        int qr = tid >> 2, qc0 = (tid & 3) * 16;
        #pragma unroll
        for (int j = 0; j < 4; j++) {
            float4 t4 = *(const float4*)&q[base + (size_t)(q0 + qr) * ld + qc0 + j * 4];
            t4.x *= 0.125f; t4.y *= 0.125f; t4.z *= 0.125f; t4.w *= 0.125f;
            *(float4*)&Qs[qr][qc0 + j * 4] = t4;
        }
    }
    float O[4][4] = {};
    float m[4], l[4];
    #pragma unroll
    for (int i = 0; i < 4; i++) { m[i] = -1e30f; l[i] = 0.f; }
    int nkt = 2 * qt + 2;
    for (int kt = 0; kt < nkt; kt++) {
        int k0 = kt * 32;
        {
            int kr = tid >> 3, dc0 = (tid & 7) * 8;
            #pragma unroll
            for (int jj = 0; jj < 8; jj++)
                Kt[dc0 + jj][kr] = k[base + (size_t)(k0 + kr) * ld + dc0 + jj];
            int vr = (kr < 32) ? kr : kr - 32;
            #pragma unroll
            for (int j = 0; j < 2; j++)
                *(float4*)&Vs[vr][dc0 + j * 4] =
                    *(const float4*)&v[base + (size_t)(k0 + vr) * ld + dc0 + j * 4];
        }
        __syncthreads();
        float S[4][2] = {};
        #pragma unroll 4
        for (int d = 0; d < 64; d++) {
            float kv0 = Kt[d][tx * 2], kv1 = Kt[d][tx * 2 + 1];
            #pragma unroll
            for (int i = 0; i < 4; i++) {
                float qv = Qs[ty * 4 + i][d];
                S[i][0] += qv * kv0;
                S[i][1] += qv * kv1;
            }
        }
        if (k0 + 31 > q0) {
            #pragma unroll
            for (int i = 0; i < 4; i++) {
                int qg = q0 + ty * 4 + i;
                #pragma unroll
                for (int j = 0; j < 2; j++)
                    if (k0 + tx * 2 + j > qg) S[i][j] = -1e30f;
            }
        }
        #pragma unroll
        for (int i = 0; i < 4; i++) {
            float rm = fmaxf(S[i][0], S[i][1]);
            #pragma unroll
            for (int off = 8; off > 0; off >>= 1)
                rm = fmaxf(rm, __shfl_xor_sync(0xffffffffu, rm, off));
            float mn = fmaxf(m[i], rm);
            float sc = __expf(m[i] - mn);
            float e0 = __expf(S[i][0] - mn);
            float e1 = __expf(S[i][1] - mn);
            S[i][0] = e0; S[i][1] = e1;
            float rs = e0 + e1;
            #pragma unroll
            for (int off = 8; off > 0; off >>= 1)
                rs += __shfl_xor_sync(0xffffffffu, rs, off);
            l[i] = l[i] * sc + rs;
            m[i] = mn;
            #pragma unroll
            for (int j = 0; j < 4; j++) O[i][j] *= sc;
        }
        #pragma unroll
        for (int i = 0; i < 4; i++) {
            Ps[ty * 4 + i][tx * 2]     = S[i][0];
            Ps[ty * 4 + i][tx * 2 + 1] = S[i][1];
        }
        __syncthreads();
        #pragma unroll 4
        for (int c = 0; c < 32; c++) {
            float4 vv = *(const float4*)&Vs[c][tx * 4];
            #pragma unroll
            for (int i = 0; i < 4; i++) {
                float pv = Ps[ty * 4 + i][c];
                O[i][0] += pv * vv.x;
                O[i][1] += pv * vv.y;
                O[i][2] += pv * vv.z;
                O[i][3] += pv * vv.w;
            }
        }
        __syncthreads();
    }
    #pragma unroll
    for (int i = 0; i < 4; i++) {
        float inv = 1.0f / l[i];
        size_t orow = obase + (size_t)(q0 + ty * 4 + i) * Dd + tx * 4;
        #pragma unroll
        for (int j = 0; j < 4; j++) o[orow + j] = O[i][j] * inv;
    }
}

// ---------------- small scalar kernels ----------------
__global__ void smalls_k(const float* aggl, const float* ml1, const float* ml2) {
    if (threadIdx.x || blockIdx.x) return;
    for (int s = 0; s < 2; s++) {
        const float* ml = s ? ml2 : ml1;
        float M0 = f32_exp(ml[0]), M1 = f32_exp(ml[1]), M2 = f32_exp(ml[2]), M3 = f32_exp(ml[3]);
        for (int it = 0; it < 10; it++) {
            float r0 = M0 + M1, r1 = M2 + M3;
            M0 /= r0; M1 /= r0; M2 /= r1; M3 /= r1;
            float c0 = M0 + M2, c1 = M1 + M3;
            M0 /= c0; M2 /= c0; M1 /= c1; M3 /= c1;
        }
        g_P[s*4+0] = M0; g_P[s*4+1] = M1; g_P[s*4+2] = M2; g_P[s*4+3] = M3;
    }
    float w[3];
    softmax3_f32(aggl[0], aggl[1], aggl[2], w);
    g_w[0] = w[0]; g_w[1] = w[1]; g_w[2] = w[2];
}

// ---------------- nash: fp64 deterministic reductions ----------------
__global__ void nash_red_k() {
    double w0 = (double)g_w[0], w1 = (double)g_w[1], w2 = (double)g_w[2];
    double s0 = 0., s1 = 0., s2 = 0.;
    for (size_t idx = (size_t)blockIdx.x * 256 + threadIdx.x; idx < (size_t)BND;
         idx += (size_t)NREDB * 256) {
        size_t bn = idx / Dd; int d = (int)(idx % Dd);
        int b = (int)(bn / Nn), n = (int)(bn % Nn);
        double z0 = (double)g_Z0[idx];
        double z1 = (double)g_Z1[((size_t)b*(Nn/2) + (n>>1)) * Dd + d];
        double z2 = (double)g_Z2[((size_t)b*(Nn/4) + (n>>2)) * Dd + d];
        double yb = w0*z0 + w1*z1 + w2*z2;
        double d0 = z0-yb, d1 = z1-yb, d2 = z2-yb;
        s0 += d0*d0; s1 += d1*d1; s2 += d2*d2;
    }
    __shared__ double red[256];
    double sv[3] = {s0, s1, s2};
    for (int lvl = 0; lvl < 3; lvl++) {
        red[threadIdx.x] = sv[lvl]; __syncthreads();
        for (int o = 128; o > 0; o >>= 1) {
            if (threadIdx.x < o) red[threadIdx.x] += red[threadIdx.x + o];
            __syncthreads();
        }
        if (threadIdx.x == 0) g_part[blockIdx.x*3 + lvl] = red[0];
        __syncthreads();
    }
}

__global__ void nash_upd_k(const float* aggl) {
    if (threadIdx.x || blockIdx.x) return;
    double s0 = 0., s1 = 0., s2 = 0.;
    for (int i = 0; i < NREDB; i++) { s0 += g_part[i*3]; s1 += g_part[i*3+1]; s2 += g_part[i*3+2]; }
    float u0 = (float)(-(s0 * (1.0 / (double)BND)));
    float u1 = (float)(-(s1 * (1.0 / (double)BND)));
    float u2 = (float)(-(s2 * (1.0 / (double)BND)));
    float w[3];
    softmax3_f32(aggl[0] + u0, aggl[1] + u1, aggl[2] + u2, w);
    g_w[0] = w[0]; g_w[1] = w[1]; g_w[2] = w[2];
}

// ---------------- residual mixes ----------------
__global__ void comb1_k(const float* __restrict__ x, float* __restrict__ x1) {
    size_t idx = (size_t)blockIdx.x * 256 + threadIdx.x;
    if (idx >= (size_t)BND) return;
    size_t bn = idx / Dd; int d = (int)(idx % Dd);
    int b = (int)(bn / Nn), n = (int)(bn % Nn);
    float ao = g_w[0]*g_Z0[idx]
             + g_w[1]*g_Z1[((size_t)b*(Nn/2) + (n>>1)) * Dd + d]
             + g_w[2]*g_Z2[((size_t)b*(Nn/4) + (n>>2)) * Dd + d];
    x1[idx] = g_P[0]*x[idx] + g_P[1]*ao;
}

__global__ void comb2_k(const float* __restrict__ x1, const float* __restrict__ ffn,
                        float* __restrict__ out) {
    size_t idx = (size_t)blockIdx.x * 256 + threadIdx.x;
    if (idx >= (size_t)BND) return;
    out[idx] = g_P[4]*x1[idx] + g_P[5]*ffn[idx];
}

// silu(gate)*up from fused [M, 5504] buffer -> compact [M, HID]
__global__ void silu2_k(const float* __restrict__ guf, float* __restrict__ h,
                        int HIDv, long long n) {
    long long idx = (long long)blockIdx.x * 256 + threadIdx.x;
    if (idx >= n) return;
    int r = (int)(idx / HIDv), j = (int)(idx % HIDv);
    float gv = guf[(size_t)r * 5504 + j];
    float uv = guf[(size_t)r * 5504 + 2752 + j];
    float sig = 1.0f / (1.0f + __expf(-gv));
    h[idx] = gv * sig * uv;
}

// ---------------- aux loss: fp32 bit-emulation ----------------
__global__ void aux_k(float* out) {
    if (threadIdx.x || blockIdx.x) return;
    float p[3];
    #pragma unroll
    for (int l = 0; l < 3; l++) {
        float w = g_w[l];
        float t = w * 3.0f;
        t = t + 1e-9f;
        float gl = f32_log(t);
        p[l] = w * gl;
    }
    out[BND] = (p[0] + p[1]) + p[2];
}

// ---------------- launcher ----------------
extern "C" void kernel_launch(void* const* d_in, const int* in_sizes, int n_in,
                              void* d_out, int out_size) {
    const float* x    = (const float*)d_in[0];
    const float* nw1  = (const float*)d_in[1];
    const float* nw2  = (const float*)d_in[2];
    const float* Wdec = (const float*)d_in[3];
    const float* Wq   = (const float*)d_in[4];
    const float* Wk   = (const float*)d_in[5];
    const float* Wv   = (const float*)d_in[6];
    const float* Wo   = (const float*)d_in[7];
    const float* aggl = (const float*)d_in[8];
    const float* wg   = (const float*)d_in[9];
    const float* wu   = (const float*)d_in[10];
    const float* wd   = (const float*)d_in[11];
    const float* ml1  = (const float*)d_in[12];
    const float* ml2  = (const float*)d_in[13];
    float* out = (float*)d_out;
    int HID = in_sizes[9] / Dd;          // 2734
    if (HID > HID_MAX) HID = HID_MAX;

    float *xn,*p1,*p2,*sc0,*sc1,*sc2,*qkv,*ao,*Z0,*Z1,*Z2,*x1,*gu,*hbuf;
    cudaGetSymbolAddress((void**)&xn,  g_xn);
    cudaGetSymbolAddress((void**)&p1,  g_p1);
    cudaGetSymbolAddress((void**)&p2,  g_p2);
    cudaGetSymbolAddress((void**)&sc0, g_sc0);
    cudaGetSymbolAddress((void**)&sc1, g_sc1);
    cudaGetSymbolAddress((void**)&sc2, g_sc2);
    cudaGetSymbolAddress((void**)&qkv, g_qkv);
    cudaGetSymbolAddress((void**)&ao,  g_ao);
    cudaGetSymbolAddress((void**)&Z0,  g_Z0);
    cudaGetSymbolAddress((void**)&Z1,  g_Z1);
    cudaGetSymbolAddress((void**)&Z2,  g_Z2);
    cudaGetSymbolAddress((void**)&x1,  g_x1);
    cudaGetSymbolAddress((void**)&gu,  g_gu);
    cudaGetSymbolAddress((void**)&hbuf,g_h);

    const unsigned DYNS = 40960;   // 2 x (128x40) halfs x 2 arrays

    auto convA = [&](const float* A, int M, int K, int stride, int wantm) {
        int Kp = (K + 63) & ~63;
        convA_k<<<(M * Kp + 255) / 256, 256>>>(A, M, K, Kp, stride, wantm);
    };
    auto convB = [&](const float* B, int K, int N, int n0, int wantm) {
        int Kp = (K + 63) & ~63;
        dim3 gb((N + 31) / 32, Kp / 32);
        convB_k<<<gb, dim3(32, 8)>>>(B, K, N, Kp, n0, wantm);
    };
    auto run = [&](float* C, int M, int Np, int K, int ldc, int npairs) {
        int Kp = (K + 63) & ~63;
        dim3 gt(Np / 128, M / 128);
        wgemm_k<<<gt, 256, DYNS>>>(C, M, ldc, Kp, npairs);
    };

    // order chosen so wgemm_k is app-launch index 3 (ncu capture slot)
    rmsnorm_k<<<Bb*Nn, 256>>>(x, nw1, xn);                       // 0
    convA(xn, Bb*Nn, Dd, Dd, 1);                                 // 1
    convB(Wdec + 0*Dd*Dd, Dd, Dd, 0, 1);                         // 2
    run(sc0, Bb*Nn, 1024, Dd, Dd, 3);                            // 3 <- profiled
    pool_k<<<(Bb*(Nn/2)*Dd + 255)/256, 256>>>(xn, p1, Bb*(Nn/2)*Dd);
    pool_k<<<(Bb*(Nn/4)*Dd + 255)/256, 256>>>(p1, p2, Bb*(Nn/4)*Dd);

    // level 0: fused QKV
    convB(Wq + 0, Dd, Dd, 0, 1);
    convB(Wk + 0, Dd, Dd, 1024, 1);
    convB(Wv,     Dd, Dd, 2048, 1);
    convA(sc0, Bb*Nn, Dd, Dd, 1);
    run(qkv, Bb*Nn, 3072, Dd, 3072, 3);
    fattn_k<<<dim3(Nn/64, Hh, Bb), 256>>>(qkv, qkv+1024, qkv+2048, ao, Nn, 3072);
    convA(ao, Bb*Nn, Dd, Dd, 1);
    convB(Wo, Dd, Dd, 0, 1);
    run(Z0, Bb*Nn, 1024, Dd, Dd, 3);

    // levels 1,2
    {
        const float* ps[2]  = {p1, p2};
        float*       scp[2] = {sc1, sc2};
        float*       Zp[2]  = {Z1, Z2};
        for (int l = 1; l < Lv; l++) {
            int nl = (l == 1) ? Nn/2 : Nn/4, M = Bb * nl;
            convA(ps[l-1], M, Dd, Dd, 1);
            convB(Wdec + (size_t)l*Dd*Dd, Dd, Dd, 0, 1);
            run(scp[l-1], M, 1024, Dd, Dd, 3);
            convA(scp[l-1], M, Dd, Dd, 1);
            convB(Wq + (size_t)l*Dd*Dd, Dd, Dd, 0, 1);
            convB(Wk + (size_t)l*Dd*Dd, Dd, Dd, 1024, 1);
            convB(Wv,                   Dd, Dd, 2048, 1);
            run(qkv, M, 3072, Dd, 3072, 3);
            fattn_k<<<dim3(nl/64, Hh, Bb), 256>>>(qkv, qkv+1024, qkv+2048, ao, nl, 3072);
            convA(ao, M, Dd, Dd, 1);
            convB(Wo, Dd, Dd, 0, 1);
            run(Zp[l-1], M, 1024, Dd, Dd, 3);
        }
    }

    // sinkhorn + nash
    smalls_k<<<1, 32>>>(aggl, ml1, ml2);
    for (int it = 0; it < 3; it++) {
        nash_red_k<<<NREDB, 256>>>();
        nash_upd_k<<<1, 32>>>(aggl);
    }

    comb1_k<<<(BND + 255)/256, 256>>>(x, x1);

    // SwiGLU FFN: single-pair fp16 (output-0 only; ample 1e-3 margin)
    rmsnorm_k<<<Bb*Nn, 256>>>(x1, nw2, xn);
    convA(xn, Bb*Nn, Dd, Dd, 0);
    convB(wg, Dd, HID, 0, 0);
    convB(wu, Dd, HID, 2752, 0);
    run(gu, Bb*Nn, 5504, Dd, 5504, 1);
    long long nh = (long long)Bb*Nn*HID;
    silu2_k<<<(unsigned)((nh + 255)/256), 256>>>(gu, hbuf, HID, nh);
    convA(hbuf, Bb*Nn, HID, HID, 0);
    convB(wd, HID, Dd, 0, 0);
    run(ao, Bb*Nn, 1024, HID, Dd, 1);

    comb2_k<<<(BND + 255)/256, 256>>>(x1, ao, out);
    if (out_size > BND) aux_k<<<1, 32>>>(out);
}